// round 11
// baseline (speedup 1.0000x reference)
#include <cuda_runtime.h>
#include <cuda_bf16.h>
#include <math.h>
#include <stdint.h>

#define Bn 8
#define Sn 4096
#define Qn 32
#define D  512
#define Hn 8
#define HD 64
#define R  256
#define SC 128
#define NC 32
#define INV_SQRT_D 0.044194173824159216f
#define ELU_CLIP 15.0f

// ---- phase1 smem ----
#define OFF_MASK 0
#define OFF_PSUM 512
#define OFF_PIPE 2048
#define TILE_B 10240              // 128 rows * 80 bytes (pitch 40 bf16)
#define STAGE_A (4 * TILE_B)      // 40960
#define SMEM_P1_BYTES (OFF_PIPE + 2 * STAGE_A)   // 83968

// ---- gemmB smem ----
#define GB_EH 0
#define GB_EL 18432               // 128 rows * 144B
#define GB_XH 36864
#define GB_XL 46080               // + 64 rows * 144B
#define STAGE_GB 55296
#define NSTAGE_GB 3
#define SMEM_GB_BYTES (NSTAGE_GB * STAGE_GB)     // 165888

__device__ float g_qp[Bn * Qn * D];
__device__ __align__(16) __nv_bfloat16 g_qth[Bn * R * D];
__device__ __align__(16) __nv_bfloat16 g_qtl[Bn * R * D];
__device__ __align__(16) __nv_bfloat16 g_Xh[Bn * Sn * D];
__device__ __align__(16) __nv_bfloat16 g_Xl[Bn * Sn * D];
__device__ __align__(16) __nv_bfloat16 g_eh[Bn * 2 * NC * 128 * 128];  // 16.8MB
__device__ __align__(16) __nv_bfloat16 g_el[Bn * 2 * NC * 128 * 128];
__device__ float g_u0[Bn * R];
__device__ float g_dp[Bn * NC * R];
__device__ float g_den[Bn * R];
__device__ float g_An[Bn * R * D];

static __device__ __forceinline__ uint32_t smem_u32(const void* p) {
    return (uint32_t)__cvta_generic_to_shared(p);
}
static __device__ __forceinline__ void ldsm4(uint32_t* r, uint32_t a) {
    asm volatile("ldmatrix.sync.aligned.m8n8.x4.shared.b16 {%0,%1,%2,%3}, [%4];"
                 : "=r"(r[0]), "=r"(r[1]), "=r"(r[2]), "=r"(r[3]) : "r"(a));
}
static __device__ __forceinline__ void ldsm4t(uint32_t* r, uint32_t a) {
    asm volatile("ldmatrix.sync.aligned.m8n8.x4.trans.shared.b16 {%0,%1,%2,%3}, [%4];"
                 : "=r"(r[0]), "=r"(r[1]), "=r"(r[2]), "=r"(r[3]) : "r"(a));
}
static __device__ __forceinline__ void mma_bf16(float* c, const uint32_t* a, uint32_t b0, uint32_t b1) {
    asm volatile(
        "mma.sync.aligned.m16n8k16.row.col.f32.bf16.bf16.f32 "
        "{%0,%1,%2,%3}, {%4,%5,%6,%7}, {%8,%9}, {%0,%1,%2,%3};"
        : "+f"(c[0]), "+f"(c[1]), "+f"(c[2]), "+f"(c[3])
        : "r"(a[0]), "r"(a[1]), "r"(a[2]), "r"(a[3]), "r"(b0), "r"(b1));
}
static __device__ __forceinline__ void cpa16(uint32_t dst, const void* src) {
    asm volatile("cp.async.cg.shared.global [%0], [%1], 16;" :: "r"(dst), "l"(src));
}
static __device__ __forceinline__ void cpa_commit() {
    asm volatile("cp.async.commit_group;");
}
static __device__ __forceinline__ uint32_t cvt2(float lo_val, float hi_val) {
    uint32_t r;
    asm("cvt.rn.bf16x2.f32 %0, %1, %2;" : "=r"(r) : "f"(hi_val), "f"(lo_val));
    return r;
}
static __device__ __forceinline__ float bflo(uint32_t p) { return __uint_as_float(p << 16); }
static __device__ __forceinline__ float bfhi(uint32_t p) { return __uint_as_float(p & 0xFFFF0000u); }
static __device__ __forceinline__ float eterm(float u, float mk) {
    float uv = u * INV_SQRT_D;
    float el = uv > 0.f ? fminf(uv, ELU_CLIP) : (__expf(uv) - 1.f);
    return __expf(el) * mk;
}

// ---------------- K0: X -> bf16 hi/lo (vectorized) ----------------
__global__ void __launch_bounds__(256) k_xcvt(const float* __restrict__ X) {
    size_t base = (size_t)(blockIdx.x * 256 + threadIdx.x) * 8;
    float4 v0 = *(const float4*)(X + base);
    float4 v1 = *(const float4*)(X + base + 4);
    float a[8] = {v0.x, v0.y, v0.z, v0.w, v1.x, v1.y, v1.z, v1.w};
    uint32_t hp[4], lp[4];
#pragma unroll
    for (int i = 0; i < 4; i++) {
        hp[i] = cvt2(a[2 * i], a[2 * i + 1]);
        lp[i] = cvt2(a[2 * i] - bflo(hp[i]), a[2 * i + 1] - bfhi(hp[i]));
    }
    *(uint4*)(g_Xh + base) = make_uint4(hp[0], hp[1], hp[2], hp[3]);
    *(uint4*)(g_Xl + base) = make_uint4(lp[0], lp[1], lp[2], lp[3]);
}

// ---------------- K1: qp = queries @ Wq^T + bq ----------------
__global__ void __launch_bounds__(256) k_qp(const float* __restrict__ queries,
                                            const float* __restrict__ Wq,
                                            const float* __restrict__ bq) {
    const int ct = blockIdx.x, b = blockIdx.y;
    __shared__ float Qs[32 * 17];
    __shared__ float Ws[16 * 132];
    const int t = threadIdx.x, tx = t & 15, ty = t >> 4;
    float acc[2][8];
#pragma unroll
    for (int i = 0; i < 2; i++)
#pragma unroll
        for (int j = 0; j < 8; j++) acc[i][j] = 0.f;

    for (int k0 = 0; k0 < D; k0 += 16) {
        __syncthreads();
        if (t < 128) {
            int qi = t >> 2, kq = t & 3;
            float4 v = *(const float4*)(queries + (b * Qn + qi) * D + k0 + kq * 4);
            Qs[qi * 17 + kq * 4 + 0] = v.x;
            Qs[qi * 17 + kq * 4 + 1] = v.y;
            Qs[qi * 17 + kq * 4 + 2] = v.z;
            Qs[qi * 17 + kq * 4 + 3] = v.w;
        }
#pragma unroll
        for (int it = 0; it < 2; it++) {
            int idx = t + it * 256;
            int c = idx >> 2, kq = idx & 3;
            float4 v = *(const float4*)(Wq + (ct * 128 + c) * D + k0 + kq * 4);
            Ws[(kq * 4 + 0) * 132 + c] = v.x;
            Ws[(kq * 4 + 1) * 132 + c] = v.y;
            Ws[(kq * 4 + 2) * 132 + c] = v.z;
            Ws[(kq * 4 + 3) * 132 + c] = v.w;
        }
        __syncthreads();
#pragma unroll
        for (int k = 0; k < 16; k++) {
            float a0 = Qs[(ty * 2 + 0) * 17 + k];
            float a1 = Qs[(ty * 2 + 1) * 17 + k];
            float bb[8];
            *(float4*)&bb[0] = *(const float4*)&Ws[k * 132 + tx * 8];
            *(float4*)&bb[4] = *(const float4*)&Ws[k * 132 + tx * 8 + 4];
#pragma unroll
            for (int j = 0; j < 8; j++) {
                acc[0][j] = fmaf(a0, bb[j], acc[0][j]);
                acc[1][j] = fmaf(a1, bb[j], acc[1][j]);
            }
        }
    }
#pragma unroll
    for (int i = 0; i < 2; i++)
#pragma unroll
        for (int j = 0; j < 8; j++) {
            int c = ct * 128 + tx * 8 + j;
            g_qp[(b * Qn + ty * 2 + i) * D + c] = acc[i][j] + __ldg(&bq[c]);
        }
}

// ---------------- K2: qt = qp_h @ Wk_h -> bf16 hi/lo; also u0 ----------------
__global__ void __launch_bounds__(512) k_qt(const float* __restrict__ Wkv,
                                            const float* __restrict__ bkv) {
    const int qi0 = blockIdx.x * 8, h = blockIdx.y, b = blockIdx.z;
    __shared__ float qps[8 * 64];
    const int t = threadIdx.x;
    if (t < 128) {
        int qi = t >> 4, dq = t & 15;
        *(float4*)&qps[qi * 64 + dq * 4] =
            *(const float4*)(g_qp + (b * Qn + qi0 + qi) * D + h * HD + dq * 4);
    }
    __syncthreads();
    if (t < 8) {
        float s = 0.f;
#pragma unroll 8
        for (int d = 0; d < 64; d++) s = fmaf(qps[t * 64 + d], __ldg(&bkv[h * HD + d]), s);
        g_u0[b * R + h * Qn + qi0 + t] = s;
    }
    float acc[8];
#pragma unroll
    for (int i = 0; i < 8; i++) acc[i] = 0.f;
#pragma unroll 8
    for (int d = 0; d < 64; d++) {
        float w = __ldg(&Wkv[(h * HD + d) * D + t]);
#pragma unroll
        for (int i = 0; i < 8; i++) acc[i] = fmaf(qps[i * 64 + d], w, acc[i]);
    }
#pragma unroll
    for (int i = 0; i < 8; i++) {
        int idx = (b * R + h * Qn + qi0 + i) * D + t;
        __nv_bfloat16 hh = __float2bfloat16(acc[i]);
        g_qth[idx] = hh;
        g_qtl[idx] = __float2bfloat16(acc[i] - __bfloat162float(hh));
    }
}

// ---------------- K3: phase1 — u = qt @ Xc^T, e -> global ----------------
// 8 warps: 4 row-warps (32 rows) x 2 col-warps (64 cols)
__global__ void __launch_bounds__(256, 2) k_phase1(const float* __restrict__ masks) {
    const int ch = blockIdx.x, b = blockIdx.y, s0 = ch * SC;
    extern __shared__ char smraw[];
    float* mask_s = (float*)(smraw + OFF_MASK);
    float* psum   = (float*)(smraw + OFF_PSUM);   // [2][128]

    const int t = threadIdx.x, w = t >> 5, l = t & 31;
    const int wr = w & 3, wc = w >> 2;
    const uint32_t smb = smem_u32(smraw);

    if (t < 128) mask_s[t] = masks[b * Sn + s0 + t];

    const __nv_bfloat16* xhb = g_Xh + (size_t)(b * Sn + s0) * D;
    const __nv_bfloat16* xlb = g_Xl + (size_t)(b * Sn + s0) * D;

    for (int p = 0; p < 2; p++) {
        const __nv_bfloat16* qhb = g_qth + (size_t)(b * R + p * 128) * D;
        const __nv_bfloat16* qlb = g_qtl + (size_t)(b * R + p * 128) * D;

        float cu[2][8][4];
#pragma unroll
        for (int m = 0; m < 2; m++)
#pragma unroll
            for (int j = 0; j < 8; j++)
#pragma unroll
                for (int i = 0; i < 4; i++) cu[m][j][i] = 0.f;

        __syncthreads();
        {
            uint32_t sb = smb + OFF_PIPE;
#pragma unroll
            for (int it = 0; it < 8; it++) {
                int tile = it >> 1;
                int g = ((it & 1) << 8) + t;
                int row = g >> 2, c16 = g & 3;
                const __nv_bfloat16* src =
                    ((tile == 0) ? qhb : (tile == 1) ? qlb : (tile == 2) ? xhb : xlb) +
                    row * D + c16 * 8;
                cpa16(sb + tile * TILE_B + row * 80 + c16 * 16, src);
            }
            cpa_commit();
        }
        for (int kc = 0; kc < 16; kc++) {
            if (kc + 1 < 16) {
                uint32_t sb = smb + OFF_PIPE + ((kc + 1) & 1) * STAGE_A;
                int d0 = (kc + 1) * 32;
#pragma unroll
                for (int it = 0; it < 8; it++) {
                    int tile = it >> 1;
                    int g = ((it & 1) << 8) + t;
                    int row = g >> 2, c16 = g & 3;
                    const __nv_bfloat16* src =
                        ((tile == 0) ? qhb : (tile == 1) ? qlb : (tile == 2) ? xhb : xlb) +
                        row * D + d0 + c16 * 8;
                    cpa16(sb + tile * TILE_B + row * 80 + c16 * 16, src);
                }
                cpa_commit();
                asm volatile("cp.async.wait_group 1;");
            } else {
                asm volatile("cp.async.wait_group 0;");
            }
            __syncthreads();
            {
                uint32_t base = smb + OFF_PIPE + (kc & 1) * STAGE_A;
                uint32_t qtH_b = base, qtL_b = base + TILE_B;
                uint32_t xH_b = base + 2 * TILE_B, xL_b = base + 3 * TILE_B;
#pragma unroll
                for (int ks = 0; ks < 2; ks++) {
                    const int k0 = ks * 16;
                    uint32_t ah[2][4], al[2][4];
#pragma unroll
                    for (int m = 0; m < 2; m++) {
                        uint32_t aoff = (uint32_t)((wr * 32 + m * 16 + (l & 15)) * 40 +
                                                   k0 + ((l >> 4) << 3)) * 2;
                        ldsm4(ah[m], qtH_b + aoff);
                        ldsm4(al[m], qtL_b + aoff);
                    }
#pragma unroll
                    for (int jb = 0; jb < 4; jb++) {
                        uint32_t boff = (uint32_t)((wc * 64 + jb * 16 + ((l >> 4) << 3) + (l & 7)) * 40 +
                                                   k0 + (((l >> 3) & 1) << 3)) * 2;
                        uint32_t bh[4], bl[4];
                        ldsm4(bh, xH_b + boff);
                        ldsm4(bl, xL_b + boff);
                        // term-major issue order: dependency distance 4
#pragma unroll
                        for (int m = 0; m < 2; m++) {
                            mma_bf16(cu[m][2 * jb], ah[m], bh[0], bh[1]);
                            mma_bf16(cu[m][2 * jb + 1], ah[m], bh[2], bh[3]);
                        }
#pragma unroll
                        for (int m = 0; m < 2; m++) {
                            mma_bf16(cu[m][2 * jb], ah[m], bl[0], bl[1]);
                            mma_bf16(cu[m][2 * jb + 1], ah[m], bl[2], bl[3]);
                        }
#pragma unroll
                        for (int m = 0; m < 2; m++) {
                            mma_bf16(cu[m][2 * jb], al[m], bh[0], bh[1]);
                            mma_bf16(cu[m][2 * jb + 1], al[m], bh[2], bh[3]);
                        }
                    }
                }
            }
            __syncthreads();
        }

        // epilogue: u -> e, write e hi/lo tiles to global, denom partials
        const size_t eb = ((size_t)(b * 2 + p) * NC + ch) * 16384;
#pragma unroll
        for (int m = 0; m < 2; m++) {
            const int rr = wr * 32 + m * 16 + (l >> 2);   // 0..127 within p
            float u0a = __ldg(&g_u0[b * R + p * 128 + rr]);
            float u0b = __ldg(&g_u0[b * R + p * 128 + rr + 8]);
            float sum0 = 0.f, sum1 = 0.f;
#pragma unroll
            for (int j = 0; j < 8; j++) {
                int col = wc * 64 + j * 8 + 2 * (l & 3);
                float m0 = mask_s[col];
                float m1 = mask_s[col + 1];
                float e0 = eterm(cu[m][j][0] + u0a, m0);
                float e1 = eterm(cu[m][j][1] + u0a, m1);
                float e2 = eterm(cu[m][j][2] + u0b, m0);
                float e3 = eterm(cu[m][j][3] + u0b, m1);
                sum0 += e0 + e1;
                sum1 += e2 + e3;
                uint32_t ph01 = cvt2(e0, e1);
                uint32_t pl01 = cvt2(e0 - bflo(ph01), e1 - bfhi(ph01));
                uint32_t ph23 = cvt2(e2, e3);
                uint32_t pl23 = cvt2(e2 - bflo(ph23), e3 - bfhi(ph23));
                *(uint32_t*)(g_eh + eb + (size_t)rr * 128 + col) = ph01;
                *(uint32_t*)(g_el + eb + (size_t)rr * 128 + col) = pl01;
                *(uint32_t*)(g_eh + eb + (size_t)(rr + 8) * 128 + col) = ph23;
                *(uint32_t*)(g_el + eb + (size_t)(rr + 8) * 128 + col) = pl23;
            }
            sum0 += __shfl_xor_sync(0xFFFFFFFFu, sum0, 1);
            sum0 += __shfl_xor_sync(0xFFFFFFFFu, sum0, 2);
            sum1 += __shfl_xor_sync(0xFFFFFFFFu, sum1, 1);
            sum1 += __shfl_xor_sync(0xFFFFFFFFu, sum1, 2);
            if ((l & 3) == 0) {
                psum[wc * 128 + rr] = sum0;
                psum[wc * 128 + rr + 8] = sum1;
            }
        }
        __syncthreads();
        if (t < 128)
            g_dp[(b * NC + ch) * R + p * 128 + t] = psum[t] + psum[128 + t];
    }
}

// ---------------- K4: denom reduce ----------------
__global__ void k_den() {
    const int b = blockIdx.x, r = threadIdx.x;
    float s = 0.f;
#pragma unroll
    for (int ch = 0; ch < NC; ch++) s += g_dp[(b * NC + ch) * R + r];
    g_den[b * R + r] = s;
}

// ---------------- K5: gemmB — A_norm = (e @ X) / den ----------------
// 8 warps: 4 row-warps (32 rows) x 2 col-warps (32 cols)
__global__ void __launch_bounds__(256) k_gemmB() {
    const int dsl = blockIdx.x, p = blockIdx.y, b = blockIdx.z;
    const int d0 = dsl * 64;
    extern __shared__ char smraw[];
    const uint32_t smb = smem_u32(smraw);
    const int t = threadIdx.x, w = t >> 5, l = t & 31;
    const int wr = w & 3, wc = w >> 2;

    const size_t ebase0 = (size_t)(b * 2 + p) * NC * 16384;

    auto load_stage = [&](int g, int slot) {
        uint32_t sb = smb + slot * STAGE_GB;
        const size_t eb = ebase0 + (size_t)(g >> 1) * 16384 + (g & 1) * 64;
#pragma unroll
        for (int it = 0; it < 4; it++) {
            int idx = it * 256 + t;
            int row = idx >> 3, c8 = idx & 7;
            cpa16(sb + GB_EH + row * 144 + c8 * 16, g_eh + eb + (size_t)row * 128 + c8 * 8);
            cpa16(sb + GB_EL + row * 144 + c8 * 16, g_el + eb + (size_t)row * 128 + c8 * 8);
        }
#pragma unroll
        for (int it = 0; it < 2; it++) {
            int idx = it * 256 + t;
            int srow = idx >> 3, c8 = idx & 7;
            size_t xo = ((size_t)b * Sn + g * 64 + srow) * D + d0 + c8 * 8;
            cpa16(sb + GB_XH + srow * 144 + c8 * 16, g_Xh + xo);
            cpa16(sb + GB_XL + srow * 144 + c8 * 16, g_Xl + xo);
        }
        cpa_commit();
    };

    float c2[2][4][4];
#pragma unroll
    for (int m = 0; m < 2; m++)
#pragma unroll
        for (int j = 0; j < 4; j++)
#pragma unroll
            for (int i = 0; i < 4; i++) c2[m][j][i] = 0.f;

    load_stage(0, 0);
    load_stage(1, 1);

    for (int g = 0; g < 64; g++) {
        if (g + 2 < 64) {
            load_stage(g + 2, (g + 2) % 3);
            asm volatile("cp.async.wait_group 2;");
        } else if (g == 62) {
            asm volatile("cp.async.wait_group 1;");
        } else {
            asm volatile("cp.async.wait_group 0;");
        }
        __syncthreads();
        uint32_t base = smb + (g % 3) * STAGE_GB;
        uint32_t EHb = base + GB_EH, ELb = base + GB_EL;
        uint32_t XHb = base + GB_XH, XLb = base + GB_XL;
#pragma unroll
        for (int ks = 0; ks < 4; ks++) {
            const int k0 = ks * 16;
            uint32_t ah[2][4], al[2][4];
#pragma unroll
            for (int m = 0; m < 2; m++) {
                uint32_t aoff = (uint32_t)((wr * 32 + m * 16 + (l & 15)) * 72 +
                                           k0 + ((l >> 4) << 3)) * 2;
                ldsm4(ah[m], EHb + aoff);
                ldsm4(al[m], ELb + aoff);
            }
#pragma unroll
            for (int jb = 0; jb < 2; jb++) {
                uint32_t boff = (uint32_t)((k0 + (((l >> 3) & 1) << 3) + (l & 7)) * 72 +
                                           wc * 32 + jb * 16 + ((l >> 4) << 3)) * 2;
                uint32_t bh[4], bl[4];
                ldsm4t(bh, XHb + boff);
                ldsm4t(bl, XLb + boff);
                // term-major issue order: dependency distance 4
#pragma unroll
                for (int m = 0; m < 2; m++) {
                    mma_bf16(c2[m][2 * jb], ah[m], bh[0], bh[1]);
                    mma_bf16(c2[m][2 * jb + 1], ah[m], bh[2], bh[3]);
                }
#pragma unroll
                for (int m = 0; m < 2; m++) {
                    mma_bf16(c2[m][2 * jb], ah[m], bl[0], bl[1]);
                    mma_bf16(c2[m][2 * jb + 1], ah[m], bl[2], bl[3]);
                }
#pragma unroll
                for (int m = 0; m < 2; m++) {
                    mma_bf16(c2[m][2 * jb], al[m], bh[0], bh[1]);
                    mma_bf16(c2[m][2 * jb + 1], al[m], bh[2], bh[3]);
                }
            }
        }
        __syncthreads();
    }

    // epilogue: normalize + write
#pragma unroll
    for (int m = 0; m < 2; m++) {
        const int rr = wr * 32 + m * 16 + (l >> 2);
        float inv0 = 1.f / __ldg(&g_den[b * R + p * 128 + rr]);
        float inv1 = 1.f / __ldg(&g_den[b * R + p * 128 + rr + 8]);
        float* dst0 = g_An + ((size_t)b * R + p * 128 + rr) * D + d0 + wc * 32 + 2 * (l & 3);
        float* dst1 = dst0 + 8 * D;
#pragma unroll
        for (int j = 0; j < 4; j++) {
            *(float2*)(dst0 + j * 8) = make_float2(c2[m][j][0] * inv0, c2[m][j][1] * inv0);
            *(float2*)(dst1 + j * 8) = make_float2(c2[m][j][2] * inv1, c2[m][j][3] * inv1);
        }
    }
}

// ---------------- K6: out = An @ Wv^T + bv ----------------
__global__ void __launch_bounds__(256) k_out(const float* __restrict__ Wkv,
                                             const float* __restrict__ bkv,
                                             float* __restrict__ out) {
    const int h = blockIdx.x, b = blockIdx.y;
    extern __shared__ float sm[];
    float* An_s = sm;
    float* Ws   = An_s + 32 * 516;
    const int t = threadIdx.x, tx = t & 7, ty = t >> 3;

#pragma unroll
    for (int it = 0; it < 16; it++) {
        int idx = t + it * 256;
        int row = idx >> 7, cq = idx & 127;
        *(float4*)&An_s[row * 516 + cq * 4] =
            *(const float4*)(g_An + (b * R + h * Qn + row) * D + cq * 4);
    }
    float acc[8];
#pragma unroll
    for (int j = 0; j < 8; j++) acc[j] = 0.f;

    for (int kt = 0; kt < 16; kt++) {
        __syncthreads();
#pragma unroll
        for (int it = 0; it < 2; it++) {
            int idx = t * 2 + it;
            int row = idx >> 3, kq = idx & 7;
            float4 v = *(const float4*)(Wkv + (D + h * HD + row) * D + kt * 32 + kq * 4);
            Ws[(kq * 4 + 0) * 68 + row] = v.x;
            Ws[(kq * 4 + 1) * 68 + row] = v.y;
            Ws[(kq * 4 + 2) * 68 + row] = v.z;
            Ws[(kq * 4 + 3) * 68 + row] = v.w;
        }
        __syncthreads();
#pragma unroll
        for (int k = 0; k < 32; k++) {
            float a = An_s[ty * 516 + kt * 32 + k];
            float bb[8];
            *(float4*)&bb[0] = *(const float4*)&Ws[k * 68 + tx * 8];
            *(float4*)&bb[4] = *(const float4*)&Ws[k * 68 + tx * 8 + 4];
#pragma unroll
            for (int j = 0; j < 8; j++) acc[j] = fmaf(a, bb[j], acc[j]);
        }
    }
#pragma unroll
    for (int j = 0; j < 8; j++) {
        int c = h * HD + tx * 8 + j;
        out[(b * Qn + ty) * D + c] = acc[j] + __ldg(&bkv[D + c]);
    }
}

extern "C" void kernel_launch(void* const* d_in, const int* in_sizes, int n_in,
                              void* d_out, int out_size) {
    const float* X       = (const float*)d_in[0];
    const float* queries = (const float*)d_in[1];
    const float* masks   = (const float*)d_in[2];
    const float* Wkv     = (const float*)d_in[3];
    const float* bkv     = (const float*)d_in[4];
    const float* Wq      = (const float*)d_in[5];
    const float* bq      = (const float*)d_in[6];
    float* out = (float*)d_out;

    const int SMEM_OUT = (32 * 516 + 32 * 68) * 4;
    cudaFuncSetAttribute(k_phase1, cudaFuncAttributeMaxDynamicSharedMemorySize, SMEM_P1_BYTES);
    cudaFuncSetAttribute(k_gemmB,  cudaFuncAttributeMaxDynamicSharedMemorySize, SMEM_GB_BYTES);
    cudaFuncSetAttribute(k_out,    cudaFuncAttributeMaxDynamicSharedMemorySize, SMEM_OUT);

    k_xcvt<<<Bn * Sn * D / (256 * 8), 256>>>(X);
    k_qp<<<dim3(4, Bn), 256>>>(queries, Wq, bq);
    k_qt<<<dim3(4, Hn, Bn), 512>>>(Wkv, bkv);
    k_phase1<<<dim3(NC, Bn), 256, SMEM_P1_BYTES>>>(masks);
    k_den<<<Bn, 256>>>();
    k_gemmB<<<dim3(8, 2, Bn), 256, SMEM_GB_BYTES>>>();
    k_out<<<dim3(Hn, Bn), 256, SMEM_OUT>>>(Wkv, bkv, out);
}

// round 12
// speedup vs baseline: 1.0753x; 1.0753x over previous
#include <cuda_runtime.h>
#include <cuda_fp16.h>
#include <math.h>
#include <stdint.h>

#define Bn 8
#define Sn 4096
#define Qn 32
#define D  512
#define Hn 8
#define HD 64
#define R  256
#define SC 128
#define NC 32
#define INV_SQRT_D 0.044194173824159216f
#define ELU_CLIP 15.0f
#define ESCALE 0.0078125f          // 2^-7: e*ESCALE fits fp16; cancels via inv=128/den

// ---- phase1 smem ----
#define OFF_MASK 0
#define OFF_PSUM 512
#define OFF_PIPE 2048
#define TILE_B 10240              // 128 rows * 80 bytes (pitch 40 fp16)
#define STAGE_A (4 * TILE_B)      // 40960
#define SMEM_P1_BYTES (OFF_PIPE + 2 * STAGE_A)   // 83968

// ---- gemmB smem ----
#define GB_EF 0                   // 128 rows * 144B  (e fp16, 64 cols)
#define GB_XH 18432               // 64 rows * 144B
#define GB_XL 27648
#define STAGE_GB 36864
#define NSTAGE_GB 3
#define SMEM_GB_BYTES (NSTAGE_GB * STAGE_GB)     // 110592

__device__ float g_qp[Bn * Qn * D];
__device__ __align__(16) __half g_qth[Bn * R * D];
__device__ __align__(16) __half g_qtl[Bn * R * D];
__device__ __align__(16) __half g_Xh[Bn * Sn * D];
__device__ __align__(16) __half g_Xl[Bn * Sn * D];
__device__ __align__(16) __half g_ef[Bn * 2 * NC * 128 * 128];  // 16.8MB, e * 2^-7
__device__ float g_u0[Bn * R];
__device__ float g_dp[Bn * NC * R];
__device__ float g_den[Bn * R];
__device__ float g_An[Bn * R * D];

static __device__ __forceinline__ uint32_t smem_u32(const void* p) {
    return (uint32_t)__cvta_generic_to_shared(p);
}
static __device__ __forceinline__ void ldsm4(uint32_t* r, uint32_t a) {
    asm volatile("ldmatrix.sync.aligned.m8n8.x4.shared.b16 {%0,%1,%2,%3}, [%4];"
                 : "=r"(r[0]), "=r"(r[1]), "=r"(r[2]), "=r"(r[3]) : "r"(a));
}
static __device__ __forceinline__ void ldsm4t(uint32_t* r, uint32_t a) {
    asm volatile("ldmatrix.sync.aligned.m8n8.x4.trans.shared.b16 {%0,%1,%2,%3}, [%4];"
                 : "=r"(r[0]), "=r"(r[1]), "=r"(r[2]), "=r"(r[3]) : "r"(a));
}
static __device__ __forceinline__ void mma_f16(float* c, const uint32_t* a, uint32_t b0, uint32_t b1) {
    asm volatile(
        "mma.sync.aligned.m16n8k16.row.col.f32.f16.f16.f32 "
        "{%0,%1,%2,%3}, {%4,%5,%6,%7}, {%8,%9}, {%0,%1,%2,%3};"
        : "+f"(c[0]), "+f"(c[1]), "+f"(c[2]), "+f"(c[3])
        : "r"(a[0]), "r"(a[1]), "r"(a[2]), "r"(a[3]), "r"(b0), "r"(b1));
}
static __device__ __forceinline__ void cpa16(uint32_t dst, const void* src) {
    asm volatile("cp.async.cg.shared.global [%0], [%1], 16;" :: "r"(dst), "l"(src));
}
static __device__ __forceinline__ void cpa_commit() {
    asm volatile("cp.async.commit_group;");
}
static __device__ __forceinline__ uint32_t cvt2h(float lo_val, float hi_val) {
    uint32_t r;
    asm("cvt.rn.f16x2.f32 %0, %1, %2;" : "=r"(r) : "f"(hi_val), "f"(lo_val));
    return r;
}
static __device__ __forceinline__ float eterm(float u, float mk) {
    float uv = u * INV_SQRT_D;
    float el = uv > 0.f ? fminf(uv, ELU_CLIP) : (__expf(uv) - 1.f);
    return __expf(el) * mk;
}

// ---------------- K0: X -> fp16 hi/lo (vectorized) ----------------
__global__ void __launch_bounds__(256) k_xcvt(const float* __restrict__ X) {
    size_t base = (size_t)(blockIdx.x * 256 + threadIdx.x) * 8;
    float4 v0 = *(const float4*)(X + base);
    float4 v1 = *(const float4*)(X + base + 4);
    float a[8] = {v0.x, v0.y, v0.z, v0.w, v1.x, v1.y, v1.z, v1.w};
    float h[8], lo[8];
#pragma unroll
    for (int i = 0; i < 8; i++) {
        h[i] = __half2float(__float2half_rn(a[i]));
        lo[i] = a[i] - h[i];
    }
    uint32_t hp[4], lp[4];
#pragma unroll
    for (int i = 0; i < 4; i++) {
        hp[i] = cvt2h(h[2 * i], h[2 * i + 1]);
        lp[i] = cvt2h(lo[2 * i], lo[2 * i + 1]);
    }
    *(uint4*)(g_Xh + base) = make_uint4(hp[0], hp[1], hp[2], hp[3]);
    *(uint4*)(g_Xl + base) = make_uint4(lp[0], lp[1], lp[2], lp[3]);
}

// ---------------- K1: qp = queries @ Wq^T + bq ----------------
__global__ void __launch_bounds__(256) k_qp(const float* __restrict__ queries,
                                            const float* __restrict__ Wq,
                                            const float* __restrict__ bq) {
    const int ct = blockIdx.x, b = blockIdx.y;
    __shared__ float Qs[32 * 17];
    __shared__ float Ws[16 * 132];
    const int t = threadIdx.x, tx = t & 15, ty = t >> 4;
    float acc[2][8];
#pragma unroll
    for (int i = 0; i < 2; i++)
#pragma unroll
        for (int j = 0; j < 8; j++) acc[i][j] = 0.f;

    for (int k0 = 0; k0 < D; k0 += 16) {
        __syncthreads();
        if (t < 128) {
            int qi = t >> 2, kq = t & 3;
            float4 v = *(const float4*)(queries + (b * Qn + qi) * D + k0 + kq * 4);
            Qs[qi * 17 + kq * 4 + 0] = v.x;
            Qs[qi * 17 + kq * 4 + 1] = v.y;
            Qs[qi * 17 + kq * 4 + 2] = v.z;
            Qs[qi * 17 + kq * 4 + 3] = v.w;
        }
#pragma unroll
        for (int it = 0; it < 2; it++) {
            int idx = t + it * 256;
            int c = idx >> 2, kq = idx & 3;
            float4 v = *(const float4*)(Wq + (ct * 128 + c) * D + k0 + kq * 4);
            Ws[(kq * 4 + 0) * 132 + c] = v.x;
            Ws[(kq * 4 + 1) * 132 + c] = v.y;
            Ws[(kq * 4 + 2) * 132 + c] = v.z;
            Ws[(kq * 4 + 3) * 132 + c] = v.w;
        }
        __syncthreads();
#pragma unroll
        for (int k = 0; k < 16; k++) {
            float a0 = Qs[(ty * 2 + 0) * 17 + k];
            float a1 = Qs[(ty * 2 + 1) * 17 + k];
            float bb[8];
            *(float4*)&bb[0] = *(const float4*)&Ws[k * 132 + tx * 8];
            *(float4*)&bb[4] = *(const float4*)&Ws[k * 132 + tx * 8 + 4];
#pragma unroll
            for (int j = 0; j < 8; j++) {
                acc[0][j] = fmaf(a0, bb[j], acc[0][j]);
                acc[1][j] = fmaf(a1, bb[j], acc[1][j]);
            }
        }
    }
#pragma unroll
    for (int i = 0; i < 2; i++)
#pragma unroll
        for (int j = 0; j < 8; j++) {
            int c = ct * 128 + tx * 8 + j;
            g_qp[(b * Qn + ty * 2 + i) * D + c] = acc[i][j] + __ldg(&bq[c]);
        }
}

// ---------------- K2: qt = qp_h @ Wk_h -> fp16 hi/lo; also u0 ----------------
__global__ void __launch_bounds__(512) k_qt(const float* __restrict__ Wkv,
                                            const float* __restrict__ bkv) {
    const int qi0 = blockIdx.x * 8, h = blockIdx.y, b = blockIdx.z;
    __shared__ float qps[8 * 64];
    const int t = threadIdx.x;
    if (t < 128) {
        int qi = t >> 4, dq = t & 15;
        *(float4*)&qps[qi * 64 + dq * 4] =
            *(const float4*)(g_qp + (b * Qn + qi0 + qi) * D + h * HD + dq * 4);
    }
    __syncthreads();
    if (t < 8) {
        float s = 0.f;
#pragma unroll 8
        for (int d = 0; d < 64; d++) s = fmaf(qps[t * 64 + d], __ldg(&bkv[h * HD + d]), s);
        g_u0[b * R + h * Qn + qi0 + t] = s;
    }
    float acc[8];
#pragma unroll
    for (int i = 0; i < 8; i++) acc[i] = 0.f;
#pragma unroll 8
    for (int d = 0; d < 64; d++) {
        float w = __ldg(&Wkv[(h * HD + d) * D + t]);
#pragma unroll
        for (int i = 0; i < 8; i++) acc[i] = fmaf(qps[i * 64 + d], w, acc[i]);
    }
#pragma unroll
    for (int i = 0; i < 8; i++) {
        int idx = (b * R + h * Qn + qi0 + i) * D + t;
        __half hh = __float2half_rn(acc[i]);
        g_qth[idx] = hh;
        g_qtl[idx] = __float2half_rn(acc[i] - __half2float(hh));
    }
}

// ---------------- K3: phase1 — u = qt @ Xc^T (3-term fp16), e -> global fp16 ----------------
// 8 warps: 4 row-warps (32 rows) x 2 col-warps (64 cols)
__global__ void __launch_bounds__(256, 2) k_phase1(const float* __restrict__ masks) {
    const int ch = blockIdx.x, b = blockIdx.y, s0 = ch * SC;
    extern __shared__ char smraw[];
    float* mask_s = (float*)(smraw + OFF_MASK);
    float* psum   = (float*)(smraw + OFF_PSUM);   // [2][128]

    const int t = threadIdx.x, w = t >> 5, l = t & 31;
    const int wr = w & 3, wc = w >> 2;
    const uint32_t smb = smem_u32(smraw);

    if (t < 128) mask_s[t] = masks[b * Sn + s0 + t];

    const __half* xhb = g_Xh + (size_t)(b * Sn + s0) * D;
    const __half* xlb = g_Xl + (size_t)(b * Sn + s0) * D;

    for (int p = 0; p < 2; p++) {
        const __half* qhb = g_qth + (size_t)(b * R + p * 128) * D;
        const __half* qlb = g_qtl + (size_t)(b * R + p * 128) * D;

        float cu[2][8][4];
#pragma unroll
        for (int m = 0; m < 2; m++)
#pragma unroll
            for (int j = 0; j < 8; j++)
#pragma unroll
                for (int i = 0; i < 4; i++) cu[m][j][i] = 0.f;

        __syncthreads();
        {
            uint32_t sb = smb + OFF_PIPE;
#pragma unroll
            for (int it = 0; it < 8; it++) {
                int tile = it >> 1;
                int g = ((it & 1) << 8) + t;
                int row = g >> 2, c16 = g & 3;
                const __half* src =
                    ((tile == 0) ? qhb : (tile == 1) ? qlb : (tile == 2) ? xhb : xlb) +
                    row * D + c16 * 8;
                cpa16(sb + tile * TILE_B + row * 80 + c16 * 16, src);
            }
            cpa_commit();
        }
        for (int kc = 0; kc < 16; kc++) {
            if (kc + 1 < 16) {
                uint32_t sb = smb + OFF_PIPE + ((kc + 1) & 1) * STAGE_A;
                int d0 = (kc + 1) * 32;
#pragma unroll
                for (int it = 0; it < 8; it++) {
                    int tile = it >> 1;
                    int g = ((it & 1) << 8) + t;
                    int row = g >> 2, c16 = g & 3;
                    const __half* src =
                        ((tile == 0) ? qhb : (tile == 1) ? qlb : (tile == 2) ? xhb : xlb) +
                        row * D + d0 + c16 * 8;
                    cpa16(sb + tile * TILE_B + row * 80 + c16 * 16, src);
                }
                cpa_commit();
                asm volatile("cp.async.wait_group 1;");
            } else {
                asm volatile("cp.async.wait_group 0;");
            }
            __syncthreads();
            {
                uint32_t base = smb + OFF_PIPE + (kc & 1) * STAGE_A;
                uint32_t qtH_b = base, qtL_b = base + TILE_B;
                uint32_t xH_b = base + 2 * TILE_B, xL_b = base + 3 * TILE_B;
#pragma unroll
                for (int ks = 0; ks < 2; ks++) {
                    const int k0 = ks * 16;
                    uint32_t ah[2][4], al[2][4];
#pragma unroll
                    for (int m = 0; m < 2; m++) {
                        uint32_t aoff = (uint32_t)((wr * 32 + m * 16 + (l & 15)) * 40 +
                                                   k0 + ((l >> 4) << 3)) * 2;
                        ldsm4(ah[m], qtH_b + aoff);
                        ldsm4(al[m], qtL_b + aoff);
                    }
#pragma unroll
                    for (int jb = 0; jb < 4; jb++) {
                        uint32_t boff = (uint32_t)((wc * 64 + jb * 16 + ((l >> 4) << 3) + (l & 7)) * 40 +
                                                   k0 + (((l >> 3) & 1) << 3)) * 2;
                        uint32_t bh[4], bl[4];
                        ldsm4(bh, xH_b + boff);
                        ldsm4(bl, xL_b + boff);
#pragma unroll
                        for (int m = 0; m < 2; m++) {
                            mma_f16(cu[m][2 * jb], ah[m], bh[0], bh[1]);
                            mma_f16(cu[m][2 * jb + 1], ah[m], bh[2], bh[3]);
                        }
#pragma unroll
                        for (int m = 0; m < 2; m++) {
                            mma_f16(cu[m][2 * jb], ah[m], bl[0], bl[1]);
                            mma_f16(cu[m][2 * jb + 1], ah[m], bl[2], bl[3]);
                        }
#pragma unroll
                        for (int m = 0; m < 2; m++) {
                            mma_f16(cu[m][2 * jb], al[m], bh[0], bh[1]);
                            mma_f16(cu[m][2 * jb + 1], al[m], bh[2], bh[3]);
                        }
                    }
                }
            }
            __syncthreads();
        }

        // epilogue: u -> e (scaled fp16), denom partials
        const size_t eb = ((size_t)(b * 2 + p) * NC + ch) * 16384;
#pragma unroll
        for (int m = 0; m < 2; m++) {
            const int rr = wr * 32 + m * 16 + (l >> 2);   // 0..127 within p
            float u0a = __ldg(&g_u0[b * R + p * 128 + rr]);
            float u0b = __ldg(&g_u0[b * R + p * 128 + rr + 8]);
            float sum0 = 0.f, sum1 = 0.f;
#pragma unroll
            for (int j = 0; j < 8; j++) {
                int col = wc * 64 + j * 8 + 2 * (l & 3);
                float m0 = mask_s[col];
                float m1 = mask_s[col + 1];
                float e0 = eterm(cu[m][j][0] + u0a, m0);
                float e1 = eterm(cu[m][j][1] + u0a, m1);
                float e2 = eterm(cu[m][j][2] + u0b, m0);
                float e3 = eterm(cu[m][j][3] + u0b, m1);
                sum0 += e0 + e1;
                sum1 += e2 + e3;
                *(uint32_t*)(g_ef + eb + (size_t)rr * 128 + col) =
                    cvt2h(e0 * ESCALE, e1 * ESCALE);
                *(uint32_t*)(g_ef + eb + (size_t)(rr + 8) * 128 + col) =
                    cvt2h(e2 * ESCALE, e3 * ESCALE);
            }
            sum0 += __shfl_xor_sync(0xFFFFFFFFu, sum0, 1);
            sum0 += __shfl_xor_sync(0xFFFFFFFFu, sum0, 2);
            sum1 += __shfl_xor_sync(0xFFFFFFFFu, sum1, 1);
            sum1 += __shfl_xor_sync(0xFFFFFFFFu, sum1, 2);
            if ((l & 3) == 0) {
                psum[wc * 128 + rr] = sum0;
                psum[wc * 128 + rr + 8] = sum1;
            }
        }
        __syncthreads();
        if (t < 128)
            g_dp[(b * NC + ch) * R + p * 128 + t] = psum[t] + psum[128 + t];
    }
}

// ---------------- K4: denom reduce ----------------
__global__ void k_den() {
    const int b = blockIdx.x, r = threadIdx.x;
    float s = 0.f;
#pragma unroll
    for (int ch = 0; ch < NC; ch++) s += g_dp[(b * NC + ch) * R + r];
    g_den[b * R + r] = s;
}

// ---------------- K5: gemmB — A_norm = (e @ X) * 128/den  (2-term fp16) ----------------
// 8 warps: 4 row-warps (32 rows) x 2 col-warps (32 cols)
__global__ void __launch_bounds__(256) k_gemmB() {
    const int dsl = blockIdx.x, p = blockIdx.y, b = blockIdx.z;
    const int d0 = dsl * 64;
    extern __shared__ char smraw[];
    const uint32_t smb = smem_u32(smraw);
    const int t = threadIdx.x, w = t >> 5, l = t & 31;
    const int wr = w & 3, wc = w >> 2;

    const size_t ebase0 = (size_t)(b * 2 + p) * NC * 16384;

    auto load_stage = [&](int g, int slot) {
        uint32_t sb = smb + slot * STAGE_GB;
        const size_t eb = ebase0 + (size_t)(g >> 1) * 16384 + (g & 1) * 64;
#pragma unroll
        for (int it = 0; it < 4; it++) {
            int idx = it * 256 + t;
            int row = idx >> 3, c8 = idx & 7;
            cpa16(sb + GB_EF + row * 144 + c8 * 16, g_ef + eb + (size_t)row * 128 + c8 * 8);
        }
#pragma unroll
        for (int it = 0; it < 2; it++) {
            int idx = it * 256 + t;
            int srow = idx >> 3, c8 = idx & 7;
            size_t xo = ((size_t)b * Sn + g * 64 + srow) * D + d0 + c8 * 8;
            cpa16(sb + GB_XH + srow * 144 + c8 * 16, g_Xh + xo);
            cpa16(sb + GB_XL + srow * 144 + c8 * 16, g_Xl + xo);
        }
        cpa_commit();
    };

    float c2[2][4][4];
#pragma unroll
    for (int m = 0; m < 2; m++)
#pragma unroll
        for (int j = 0; j < 4; j++)
#pragma unroll
            for (int i = 0; i < 4; i++) c2[m][j][i] = 0.f;

    load_stage(0, 0);
    load_stage(1, 1);

    for (int g = 0; g < 64; g++) {
        if (g + 2 < 64) {
            load_stage(g + 2, (g + 2) % 3);
            asm volatile("cp.async.wait_group 2;");
        } else if (g == 62) {
            asm volatile("cp.async.wait_group 1;");
        } else {
            asm volatile("cp.async.wait_group 0;");
        }
        __syncthreads();
        uint32_t base = smb + (g % 3) * STAGE_GB;
        uint32_t EFb = base + GB_EF;
        uint32_t XHb = base + GB_XH, XLb = base + GB_XL;
#pragma unroll
        for (int ks = 0; ks < 4; ks++) {
            const int k0 = ks * 16;
            uint32_t ah[2][4];
#pragma unroll
            for (int m = 0; m < 2; m++) {
                uint32_t aoff = (uint32_t)((wr * 32 + m * 16 + (l & 15)) * 72 +
                                           k0 + ((l >> 4) << 3)) * 2;
                ldsm4(ah[m], EFb + aoff);
            }
#pragma unroll
            for (int jb = 0; jb < 2; jb++) {
                uint32_t boff = (uint32_t)((k0 + (((l >> 3) & 1) << 3) + (l & 7)) * 72 +
                                           wc * 32 + jb * 16 + ((l >> 4) << 3)) * 2;
                uint32_t bh[4], bl[4];
                ldsm4t(bh, XHb + boff);
                ldsm4t(bl, XLb + boff);
#pragma unroll
                for (int m = 0; m < 2; m++) {
                    mma_f16(c2[m][2 * jb], ah[m], bh[0], bh[1]);
                    mma_f16(c2[m][2 * jb + 1], ah[m], bh[2], bh[3]);
                }
#pragma unroll
                for (int m = 0; m < 2; m++) {
                    mma_f16(c2[m][2 * jb], ah[m], bl[0], bl[1]);
                    mma_f16(c2[m][2 * jb + 1], ah[m], bl[2], bl[3]);
                }
            }
        }
        __syncthreads();
    }

    // epilogue: normalize (scale 2^7 folds the e*2^-7) + write
#pragma unroll
    for (int m = 0; m < 2; m++) {
        const int rr = wr * 32 + m * 16 + (l >> 2);
        float inv0 = 128.f / __ldg(&g_den[b * R + p * 128 + rr]);
        float inv1 = 128.f / __ldg(&g_den[b * R + p * 128 + rr + 8]);
        float* dst0 = g_An + ((size_t)b * R + p * 128 + rr) * D + d0 + wc * 32 + 2 * (l & 3);
        float* dst1 = dst0 + 8 * D;
#pragma unroll
        for (int j = 0; j < 4; j++) {
            *(float2*)(dst0 + j * 8) = make_float2(c2[m][j][0] * inv0, c2[m][j][1] * inv0);
            *(float2*)(dst1 + j * 8) = make_float2(c2[m][j][2] * inv1, c2[m][j][3] * inv1);
        }
    }
}

// ---------------- K6: out = An @ Wv^T + bv ----------------
__global__ void __launch_bounds__(256) k_out(const float* __restrict__ Wkv,
                                             const float* __restrict__ bkv,
                                             float* __restrict__ out) {
    const int h = blockIdx.x, b = blockIdx.y;
    extern __shared__ float sm[];
    float* An_s = sm;
    float* Ws   = An_s + 32 * 516;
    const int t = threadIdx.x, tx = t & 7, ty = t >> 3;

#pragma unroll
    for (int it = 0; it < 16; it++) {
        int idx = t + it * 256;
        int row = idx >> 7, cq = idx & 127;
        *(float4*)&An_s[row * 516 + cq * 4] =
            *(const float4*)(g_An + (b * R + h * Qn + row) * D + cq * 4);
    }
    float acc[8];
#pragma unroll
    for (int j = 0; j < 8; j++) acc[j] = 0.f;

    for (int kt = 0; kt < 16; kt++) {
        __syncthreads();
#pragma unroll
        for (int it = 0; it < 2; it++) {
            int idx = t * 2 + it;
            int row = idx >> 3, kq = idx & 7;
            float4 v = *(const float4*)(Wkv + (D + h * HD + row) * D + kt * 32 + kq * 4);
            Ws[(kq * 4 + 0) * 68 + row] = v.x;
            Ws[(kq * 4 + 1) * 68 + row] = v.y;
            Ws[(kq * 4 + 2) * 68 + row] = v.z;
            Ws[(kq * 4 + 3) * 68 + row] = v.w;
        }
        __syncthreads();
#pragma unroll
        for (int k = 0; k < 32; k++) {
            float a = An_s[ty * 516 + kt * 32 + k];
            float bb[8];
            *(float4*)&bb[0] = *(const float4*)&Ws[k * 68 + tx * 8];
            *(float4*)&bb[4] = *(const float4*)&Ws[k * 68 + tx * 8 + 4];
#pragma unroll
            for (int j = 0; j < 8; j++) acc[j] = fmaf(a, bb[j], acc[j]);
        }
    }
#pragma unroll
    for (int j = 0; j < 8; j++) {
        int c = h * HD + tx * 8 + j;
        out[(b * Qn + ty) * D + c] = acc[j] + __ldg(&bkv[D + c]);
    }
}

extern "C" void kernel_launch(void* const* d_in, const int* in_sizes, int n_in,
                              void* d_out, int out_size) {
    const float* X       = (const float*)d_in[0];
    const float* queries = (const float*)d_in[1];
    const float* masks   = (const float*)d_in[2];
    const float* Wkv     = (const float*)d_in[3];
    const float* bkv     = (const float*)d_in[4];
    const float* Wq      = (const float*)d_in[5];
    const float* bq      = (const float*)d_in[6];
    float* out = (float*)d_out;

    const int SMEM_OUT = (32 * 516 + 32 * 68) * 4;
    cudaFuncSetAttribute(k_phase1, cudaFuncAttributeMaxDynamicSharedMemorySize, SMEM_P1_BYTES);
    cudaFuncSetAttribute(k_gemmB,  cudaFuncAttributeMaxDynamicSharedMemorySize, SMEM_GB_BYTES);
    cudaFuncSetAttribute(k_out,    cudaFuncAttributeMaxDynamicSharedMemorySize, SMEM_OUT);

    k_xcvt<<<Bn * Sn * D / (256 * 8), 256>>>(X);
    k_qp<<<dim3(4, Bn), 256>>>(queries, Wq, bq);
    k_qt<<<dim3(4, Hn, Bn), 512>>>(Wkv, bkv);
    k_phase1<<<dim3(NC, Bn), 256, SMEM_P1_BYTES>>>(masks);
    k_den<<<Bn, 256>>>();
    k_gemmB<<<dim3(8, 2, Bn), 256, SMEM_GB_BYTES>>>();
    k_out<<<dim3(Hn, Bn), 256, SMEM_OUT>>>(Wkv, bkv, out);
}

// round 13
// speedup vs baseline: 1.1125x; 1.0346x over previous
#include <cuda_runtime.h>
#include <cuda_fp16.h>
#include <math.h>
#include <stdint.h>

#define Bn 8
#define Sn 4096
#define Qn 32
#define D  512
#define Hn 8
#define HD 64
#define R  256
#define SC 128
#define NC 32
#define INV_SQRT_D 0.044194173824159216f
#define ELU_CLIP 15.0f
#define ESCALE 0.0078125f          // 2^-7

// ---- phase1 smem (fused p): QH/QL 256x40, XH/XL 128x40, pitch 40 halfs ----
#define OFF_MASK 0
#define OFF_PSUM 512               // 4*128 floats
#define OFF_PIPE 4096
#define P1_QH 0
#define P1_QL 20480
#define P1_XH 40960
#define P1_XL 51200
#define STAGE_P1 61440
#define SMEM_P1_BYTES (OFF_PIPE + 2 * STAGE_P1)   // 126976

// ---- gemmB smem (fused p): EF 256x72, XH/XL 64x72 halfs ----
#define GB_EF 0
#define GB_XH 36864
#define GB_XL 46080
#define STAGE_GB 55296
#define SMEM_GB_BYTES (3 * STAGE_GB)              // 165888

__device__ float g_qp[Bn * Qn * D];
__device__ __align__(16) __half g_qth[Bn * R * D];
__device__ __align__(16) __half g_qtl[Bn * R * D];
__device__ __align__(16) __half g_Xh[Bn * Sn * D];
__device__ __align__(16) __half g_Xl[Bn * Sn * D];
__device__ __align__(16) __half g_ef[Bn * 2 * NC * 128 * 128];  // e * 2^-7
__device__ float g_u0[Bn * R];
__device__ float g_dp[Bn * NC * R];
__device__ float g_den[Bn * R];
__device__ float g_Ap2[2 * Bn * R * D];   // S-half partials (8.4MB)
__device__ float g_An[Bn * R * D];

static __device__ __forceinline__ uint32_t smem_u32(const void* p) {
    return (uint32_t)__cvta_generic_to_shared(p);
}
static __device__ __forceinline__ void ldsm4(uint32_t* r, uint32_t a) {
    asm volatile("ldmatrix.sync.aligned.m8n8.x4.shared.b16 {%0,%1,%2,%3}, [%4];"
                 : "=r"(r[0]), "=r"(r[1]), "=r"(r[2]), "=r"(r[3]) : "r"(a));
}
static __device__ __forceinline__ void ldsm4t(uint32_t* r, uint32_t a) {
    asm volatile("ldmatrix.sync.aligned.m8n8.x4.trans.shared.b16 {%0,%1,%2,%3}, [%4];"
                 : "=r"(r[0]), "=r"(r[1]), "=r"(r[2]), "=r"(r[3]) : "r"(a));
}
static __device__ __forceinline__ void mma_f16(float* c, const uint32_t* a, uint32_t b0, uint32_t b1) {
    asm volatile(
        "mma.sync.aligned.m16n8k16.row.col.f32.f16.f16.f32 "
        "{%0,%1,%2,%3}, {%4,%5,%6,%7}, {%8,%9}, {%0,%1,%2,%3};"
        : "+f"(c[0]), "+f"(c[1]), "+f"(c[2]), "+f"(c[3])
        : "r"(a[0]), "r"(a[1]), "r"(a[2]), "r"(a[3]), "r"(b0), "r"(b1));
}
static __device__ __forceinline__ void cpa16(uint32_t dst, const void* src) {
    asm volatile("cp.async.cg.shared.global [%0], [%1], 16;" :: "r"(dst), "l"(src));
}
static __device__ __forceinline__ void cpa_commit() {
    asm volatile("cp.async.commit_group;");
}
static __device__ __forceinline__ uint32_t cvt2h(float lo_val, float hi_val) {
    uint32_t r;
    asm("cvt.rn.f16x2.f32 %0, %1, %2;" : "=r"(r) : "f"(hi_val), "f"(lo_val));
    return r;
}
static __device__ __forceinline__ float eterm(float u, float mk) {
    float uv = u * INV_SQRT_D;
    float el = uv > 0.f ? fminf(uv, ELU_CLIP) : (__expf(uv) - 1.f);
    return __expf(el) * mk;
}

// ---------------- K0: X -> fp16 hi/lo ----------------
__global__ void __launch_bounds__(256) k_xcvt(const float* __restrict__ X) {
    size_t base = (size_t)(blockIdx.x * 256 + threadIdx.x) * 8;
    float4 v0 = *(const float4*)(X + base);
    float4 v1 = *(const float4*)(X + base + 4);
    float a[8] = {v0.x, v0.y, v0.z, v0.w, v1.x, v1.y, v1.z, v1.w};
    float h[8], lo[8];
#pragma unroll
    for (int i = 0; i < 8; i++) {
        h[i] = __half2float(__float2half_rn(a[i]));
        lo[i] = a[i] - h[i];
    }
    uint32_t hp[4], lp[4];
#pragma unroll
    for (int i = 0; i < 4; i++) {
        hp[i] = cvt2h(h[2 * i], h[2 * i + 1]);
        lp[i] = cvt2h(lo[2 * i], lo[2 * i + 1]);
    }
    *(uint4*)(g_Xh + base) = make_uint4(hp[0], hp[1], hp[2], hp[3]);
    *(uint4*)(g_Xl + base) = make_uint4(lp[0], lp[1], lp[2], lp[3]);
}

// ---------------- K1: qp = queries @ Wq^T + bq ----------------
__global__ void __launch_bounds__(256) k_qp(const float* __restrict__ queries,
                                            const float* __restrict__ Wq,
                                            const float* __restrict__ bq) {
    const int ct = blockIdx.x, b = blockIdx.y;
    __shared__ float Qs[32 * 17];
    __shared__ float Ws[16 * 132];
    const int t = threadIdx.x, tx = t & 15, ty = t >> 4;
    float acc[2][8];
#pragma unroll
    for (int i = 0; i < 2; i++)
#pragma unroll
        for (int j = 0; j < 8; j++) acc[i][j] = 0.f;

    for (int k0 = 0; k0 < D; k0 += 16) {
        __syncthreads();
        if (t < 128) {
            int qi = t >> 2, kq = t & 3;
            float4 v = *(const float4*)(queries + (b * Qn + qi) * D + k0 + kq * 4);
            Qs[qi * 17 + kq * 4 + 0] = v.x;
            Qs[qi * 17 + kq * 4 + 1] = v.y;
            Qs[qi * 17 + kq * 4 + 2] = v.z;
            Qs[qi * 17 + kq * 4 + 3] = v.w;
        }
#pragma unroll
        for (int it = 0; it < 2; it++) {
            int idx = t + it * 256;
            int c = idx >> 2, kq = idx & 3;
            float4 v = *(const float4*)(Wq + (ct * 128 + c) * D + k0 + kq * 4);
            Ws[(kq * 4 + 0) * 132 + c] = v.x;
            Ws[(kq * 4 + 1) * 132 + c] = v.y;
            Ws[(kq * 4 + 2) * 132 + c] = v.z;
            Ws[(kq * 4 + 3) * 132 + c] = v.w;
        }
        __syncthreads();
#pragma unroll
        for (int k = 0; k < 16; k++) {
            float a0 = Qs[(ty * 2 + 0) * 17 + k];
            float a1 = Qs[(ty * 2 + 1) * 17 + k];
            float bb[8];
            *(float4*)&bb[0] = *(const float4*)&Ws[k * 132 + tx * 8];
            *(float4*)&bb[4] = *(const float4*)&Ws[k * 132 + tx * 8 + 4];
#pragma unroll
            for (int j = 0; j < 8; j++) {
                acc[0][j] = fmaf(a0, bb[j], acc[0][j]);
                acc[1][j] = fmaf(a1, bb[j], acc[1][j]);
            }
        }
    }
#pragma unroll
    for (int i = 0; i < 2; i++)
#pragma unroll
        for (int j = 0; j < 8; j++) {
            int c = ct * 128 + tx * 8 + j;
            g_qp[(b * Qn + ty * 2 + i) * D + c] = acc[i][j] + __ldg(&bq[c]);
        }
}

// ---------------- K2: qt -> fp16 hi/lo; u0 ----------------
__global__ void __launch_bounds__(512) k_qt(const float* __restrict__ Wkv,
                                            const float* __restrict__ bkv) {
    const int qi0 = blockIdx.x * 8, h = blockIdx.y, b = blockIdx.z;
    __shared__ float qps[8 * 64];
    const int t = threadIdx.x;
    if (t < 128) {
        int qi = t >> 4, dq = t & 15;
        *(float4*)&qps[qi * 64 + dq * 4] =
            *(const float4*)(g_qp + (b * Qn + qi0 + qi) * D + h * HD + dq * 4);
    }
    __syncthreads();
    if (t < 8) {
        float s = 0.f;
#pragma unroll 8
        for (int d = 0; d < 64; d++) s = fmaf(qps[t * 64 + d], __ldg(&bkv[h * HD + d]), s);
        g_u0[b * R + h * Qn + qi0 + t] = s;
    }
    float acc[8];
#pragma unroll
    for (int i = 0; i < 8; i++) acc[i] = 0.f;
#pragma unroll 8
    for (int d = 0; d < 64; d++) {
        float w = __ldg(&Wkv[(h * HD + d) * D + t]);
#pragma unroll
        for (int i = 0; i < 8; i++) acc[i] = fmaf(qps[i * 64 + d], w, acc[i]);
    }
#pragma unroll
    for (int i = 0; i < 8; i++) {
        int idx = (b * R + h * Qn + qi0 + i) * D + t;
        __half hh = __float2half_rn(acc[i]);
        g_qth[idx] = hh;
        g_qtl[idx] = __float2half_rn(acc[i] - __half2float(hh));
    }
}

// ---------------- K3: phase1 fused-p — u = qt @ Xc^T, e -> global ----------------
// 16 warps: p = w>>3; within p: 4 row-warps (32 rows) x 2 col-warps (64 cols)
__global__ void __launch_bounds__(512, 1) k_phase1(const float* __restrict__ masks) {
    const int ch = blockIdx.x, b = blockIdx.y, s0 = ch * SC;
    extern __shared__ char smraw[];
    float* mask_s = (float*)(smraw + OFF_MASK);
    float* psum   = (float*)(smraw + OFF_PSUM);   // [p][wc][128]

    const int t = threadIdx.x, w = t >> 5, l = t & 31;
    const int p = w >> 3, wr = w & 3, wc = (w >> 2) & 1;
    const uint32_t smb = smem_u32(smraw);

    if (t < 128) mask_s[t] = masks[b * Sn + s0 + t];

    const __half* xhb = g_Xh + (size_t)(b * Sn + s0) * D;
    const __half* xlb = g_Xl + (size_t)(b * Sn + s0) * D;
    const __half* qhb = g_qth + (size_t)(b * R) * D;   // all 256 rows
    const __half* qlb = g_qtl + (size_t)(b * R) * D;

    float cu[2][8][4];
#pragma unroll
    for (int m = 0; m < 2; m++)
#pragma unroll
        for (int j = 0; j < 8; j++)
#pragma unroll
            for (int i = 0; i < 4; i++) cu[m][j][i] = 0.f;

    auto load_stage = [&](int kc, int slot) {
        uint32_t sb = smb + OFF_PIPE + slot * STAGE_P1;
        int d0 = kc * 32;
#pragma unroll
        for (int it = 0; it < 2; it++) {
            int idx = it * 512 + t;
            int row = idx >> 2, c16 = idx & 3;
            cpa16(sb + P1_QH + row * 80 + c16 * 16, qhb + row * D + d0 + c16 * 8);
            cpa16(sb + P1_QL + row * 80 + c16 * 16, qlb + row * D + d0 + c16 * 8);
        }
        {
            int row = t >> 2, c16 = t & 3;
            cpa16(sb + P1_XH + row * 80 + c16 * 16, xhb + row * D + d0 + c16 * 8);
            cpa16(sb + P1_XL + row * 80 + c16 * 16, xlb + row * D + d0 + c16 * 8);
        }
        cpa_commit();
    };

    load_stage(0, 0);
    for (int kc = 0; kc < 16; kc++) {
        if (kc + 1 < 16) {
            load_stage(kc + 1, (kc + 1) & 1);
            asm volatile("cp.async.wait_group 1;");
        } else {
            asm volatile("cp.async.wait_group 0;");
        }
        __syncthreads();
        uint32_t base = smb + OFF_PIPE + (kc & 1) * STAGE_P1;
        uint32_t qtH_b = base + P1_QH, qtL_b = base + P1_QL;
        uint32_t xH_b = base + P1_XH, xL_b = base + P1_XL;
#pragma unroll
        for (int ks = 0; ks < 2; ks++) {
            const int k0 = ks * 16;
            uint32_t ah[2][4], al[2][4];
#pragma unroll
            for (int m = 0; m < 2; m++) {
                uint32_t aoff = (uint32_t)((p * 128 + wr * 32 + m * 16 + (l & 15)) * 40 +
                                           k0 + ((l >> 4) << 3)) * 2;
                ldsm4(ah[m], qtH_b + aoff);
                ldsm4(al[m], qtL_b + aoff);
            }
#pragma unroll
            for (int jb = 0; jb < 4; jb++) {
                uint32_t boff = (uint32_t)((wc * 64 + jb * 16 + ((l >> 4) << 3) + (l & 7)) * 40 +
                                           k0 + (((l >> 3) & 1) << 3)) * 2;
                uint32_t bh[4], bl[4];
                ldsm4(bh, xH_b + boff);
                ldsm4(bl, xL_b + boff);
#pragma unroll
                for (int m = 0; m < 2; m++) {
                    mma_f16(cu[m][2 * jb], ah[m], bh[0], bh[1]);
                    mma_f16(cu[m][2 * jb + 1], ah[m], bh[2], bh[3]);
                }
#pragma unroll
                for (int m = 0; m < 2; m++) {
                    mma_f16(cu[m][2 * jb], ah[m], bl[0], bl[1]);
                    mma_f16(cu[m][2 * jb + 1], ah[m], bl[2], bl[3]);
                }
#pragma unroll
                for (int m = 0; m < 2; m++) {
                    mma_f16(cu[m][2 * jb], al[m], bh[0], bh[1]);
                    mma_f16(cu[m][2 * jb + 1], al[m], bh[2], bh[3]);
                }
            }
        }
        __syncthreads();
    }

    // epilogue: u -> e (scaled fp16), denom partials
    const size_t eb = ((size_t)(b * 2 + p) * NC + ch) * 16384;
#pragma unroll
    for (int m = 0; m < 2; m++) {
        const int rr = wr * 32 + m * 16 + (l >> 2);   // 0..127 within p
        float u0a = __ldg(&g_u0[b * R + p * 128 + rr]);
        float u0b = __ldg(&g_u0[b * R + p * 128 + rr + 8]);
        float sum0 = 0.f, sum1 = 0.f;
#pragma unroll
        for (int j = 0; j < 8; j++) {
            int col = wc * 64 + j * 8 + 2 * (l & 3);
            float m0 = mask_s[col];
            float m1 = mask_s[col + 1];
            float e0 = eterm(cu[m][j][0] + u0a, m0);
            float e1 = eterm(cu[m][j][1] + u0a, m1);
            float e2 = eterm(cu[m][j][2] + u0b, m0);
            float e3 = eterm(cu[m][j][3] + u0b, m1);
            sum0 += e0 + e1;
            sum1 += e2 + e3;
            *(uint32_t*)(g_ef + eb + (size_t)rr * 128 + col) =
                cvt2h(e0 * ESCALE, e1 * ESCALE);
            *(uint32_t*)(g_ef + eb + (size_t)(rr + 8) * 128 + col) =
                cvt2h(e2 * ESCALE, e3 * ESCALE);
        }
        sum0 += __shfl_xor_sync(0xFFFFFFFFu, sum0, 1);
        sum0 += __shfl_xor_sync(0xFFFFFFFFu, sum0, 2);
        sum1 += __shfl_xor_sync(0xFFFFFFFFu, sum1, 1);
        sum1 += __shfl_xor_sync(0xFFFFFFFFu, sum1, 2);
        if ((l & 3) == 0) {
            psum[(p * 2 + wc) * 128 + rr] = sum0;
            psum[(p * 2 + wc) * 128 + rr + 8] = sum1;
        }
    }
    __syncthreads();
    if (t < 256) {
        int pp = t >> 7, r = t & 127;
        g_dp[(b * NC + ch) * R + pp * 128 + r] =
            psum[(pp * 2) * 128 + r] + psum[(pp * 2 + 1) * 128 + r];
    }
}

// ---------------- K4: denom reduce ----------------
__global__ void k_den() {
    const int b = blockIdx.x, r = threadIdx.x;
    float s = 0.f;
#pragma unroll
    for (int ch = 0; ch < NC; ch++) s += g_dp[(b * NC + ch) * R + r];
    g_den[b * R + r] = s;
}

// ---------------- K5: gemmB fused-p — partial A = e @ X over S-half ----------------
// grid (8 dsl, 2 sh, 8 b); 16 warps: p = w>>3; 4 row-warps x 2 col-warps (32 cols)
__global__ void __launch_bounds__(512, 1) k_gemmB() {
    const int dsl = blockIdx.x, sh = blockIdx.y, b = blockIdx.z;
    const int d0 = dsl * 64;
    extern __shared__ char smraw[];
    const uint32_t smb = smem_u32(smraw);
    const int t = threadIdx.x, w = t >> 5, l = t & 31;
    const int p = w >> 3, wr = w & 3, wc = (w >> 2) & 1;

    auto load_stage = [&](int g, int slot) {
        uint32_t sb = smb + slot * STAGE_GB;
        int s64 = sh * 32 + g;
        int ch = s64 >> 1, coloff = (s64 & 1) * 64;
#pragma unroll
        for (int it = 0; it < 4; it++) {
            int idx = it * 512 + t;
            int row = idx >> 3, c8 = idx & 7;
            int pr = row >> 7, rin = row & 127;
            const __half* src = g_ef + ((size_t)(b * 2 + pr) * NC + ch) * 16384 +
                                (size_t)rin * 128 + coloff + c8 * 8;
            cpa16(sb + GB_EF + row * 144 + c8 * 16, src);
        }
        {
            int srow = t >> 3, c8 = t & 7;
            size_t xo = ((size_t)b * Sn + s64 * 64 + srow) * D + d0 + c8 * 8;
            cpa16(sb + GB_XH + srow * 144 + c8 * 16, g_Xh + xo);
            cpa16(sb + GB_XL + srow * 144 + c8 * 16, g_Xl + xo);
        }
        cpa_commit();
    };

    float c2[2][4][4];
#pragma unroll
    for (int m = 0; m < 2; m++)
#pragma unroll
        for (int j = 0; j < 4; j++)
#pragma unroll
            for (int i = 0; i < 4; i++) c2[m][j][i] = 0.f;

    load_stage(0, 0);
    load_stage(1, 1);

    for (int g = 0; g < 32; g++) {
        if (g + 2 < 32) {
            load_stage(g + 2, (g + 2) % 3);
            asm volatile("cp.async.wait_group 2;");
        } else if (g == 30) {
            asm volatile("cp.async.wait_group 1;");
        } else {
            asm volatile("cp.async.wait_group 0;");
        }
        __syncthreads();
        uint32_t base = smb + (g % 3) * STAGE_GB;
        uint32_t EFb = base + GB_EF;
        uint32_t XHb = base + GB_XH, XLb = base + GB_XL;
#pragma unroll
        for (int ks = 0; ks < 4; ks++) {
            const int k0 = ks * 16;
            uint32_t ah[2][4];
#pragma unroll
            for (int m = 0; m < 2; m++) {
                uint32_t aoff = (uint32_t)((p * 128 + wr * 32 + m * 16 + (l & 15)) * 72 +
                                           k0 + ((l >> 4) << 3)) * 2;
                ldsm4(ah[m], EFb + aoff);
            }
#pragma unroll
            for (int jb = 0; jb < 2; jb++) {
                uint32_t boff = (uint32_t)((k0 + (((l >> 3) & 1) << 3) + (l & 7)) * 72 +
                                           wc * 32 + jb * 16 + ((l >> 4) << 3)) * 2;
                uint32_t bh[4], bl[4];
                ldsm4t(bh, XHb + boff);
                ldsm4t(bl, XLb + boff);
#pragma unroll
                for (int m = 0; m < 2; m++) {
                    mma_f16(c2[m][2 * jb], ah[m], bh[0], bh[1]);
                    mma_f16(c2[m][2 * jb + 1], ah[m], bh[2], bh[3]);
                }
#pragma unroll
                for (int m = 0; m < 2; m++) {
                    mma_f16(c2[m][2 * jb], ah[m], bl[0], bl[1]);
                    mma_f16(c2[m][2 * jb + 1], ah[m], bl[2], bl[3]);
                }
            }
        }
        __syncthreads();
    }

    // epilogue: raw partial write
#pragma unroll
    for (int m = 0; m < 2; m++) {
        const int rr = wr * 32 + m * 16 + (l >> 2);
        float* dst0 = g_Ap2 + ((size_t)(sh * Bn + b) * R + p * 128 + rr) * D +
                      d0 + wc * 32 + 2 * (l & 3);
        float* dst1 = dst0 + 8 * D;
#pragma unroll
        for (int j = 0; j < 4; j++) {
            *(float2*)(dst0 + j * 8) = make_float2(c2[m][j][0], c2[m][j][1]);
            *(float2*)(dst1 + j * 8) = make_float2(c2[m][j][2], c2[m][j][3]);
        }
    }
}

// ---------------- K5b: reduce 2 S-half partials + normalize ----------------
__global__ void __launch_bounds__(256) k_ared() {
    int gidx = blockIdx.x * 256 + threadIdx.x;   // float4 idx, 262144 total
    int b = gidx >> 15;
    int r = (gidx >> 7) & 255;
    int c4 = gidx & 127;
    const float4* A0 = (const float4*)g_Ap2;
    float4 v0 = A0[((size_t)b * R + r) * 128 + c4];
    float4 v1 = A0[((size_t)(Bn + b) * R + r) * 128 + c4];
    float inv = 128.f / g_den[b * R + r];
    float4 o;
    o.x = (v0.x + v1.x) * inv;
    o.y = (v0.y + v1.y) * inv;
    o.z = (v0.z + v1.z) * inv;
    o.w = (v0.w + v1.w) * inv;
    ((float4*)g_An)[((size_t)b * R + r) * 128 + c4] = o;
}

// ---------------- K6: out = An @ Wv^T + bv ----------------
__global__ void __launch_bounds__(256) k_out(const float* __restrict__ Wkv,
                                             const float* __restrict__ bkv,
                                             float* __restrict__ out) {
    const int h = blockIdx.x, b = blockIdx.y;
    extern __shared__ float sm[];
    float* An_s = sm;
    float* Ws   = An_s + 32 * 516;
    const int t = threadIdx.x, tx = t & 7, ty = t >> 3;

#pragma unroll
    for (int it = 0; it < 16; it++) {
        int idx = t + it * 256;
        int row = idx >> 7, cq = idx & 127;
        *(float4*)&An_s[row * 516 + cq * 4] =
            *(const float4*)(g_An + (b * R + h * Qn + row) * D + cq * 4);
    }
    float acc[8];
#pragma unroll
    for (int j = 0; j < 8; j++) acc[j] = 0.f;

    for (int kt = 0; kt < 16; kt++) {
        __syncthreads();
#pragma unroll
        for (int it = 0; it < 2; it++) {
            int idx = t * 2 + it;
            int row = idx >> 3, kq = idx & 7;
            float4 v = *(const float4*)(Wkv + (D + h * HD + row) * D + kt * 32 + kq * 4);
            Ws[(kq * 4 + 0) * 68 + row] = v.x;
            Ws[(kq * 4 + 1) * 68 + row] = v.y;
            Ws[(kq * 4 + 2) * 68 + row] = v.z;
            Ws[(kq * 4 + 3) * 68 + row] = v.w;
        }
        __syncthreads();
#pragma unroll
        for (int k = 0; k < 32; k++) {
            float a = An_s[ty * 516 + kt * 32 + k];
            float bb[8];
            *(float4*)&bb[0] = *(const float4*)&Ws[k * 68 + tx * 8];
            *(float4*)&bb[4] = *(const float4*)&Ws[k * 68 + tx * 8 + 4];
#pragma unroll
            for (int j = 0; j < 8; j++) acc[j] = fmaf(a, bb[j], acc[j]);
        }
    }
#pragma unroll
    for (int j = 0; j < 8; j++) {
        int c = h * HD + tx * 8 + j;
        out[(b * Qn + ty) * D + c] = acc[j] + __ldg(&bkv[D + c]);
    }
}

extern "C" void kernel_launch(void* const* d_in, const int* in_sizes, int n_in,
                              void* d_out, int out_size) {
    const float* X       = (const float*)d_in[0];
    const float* queries = (const float*)d_in[1];
    const float* masks   = (const float*)d_in[2];
    const float* Wkv     = (const float*)d_in[3];
    const float* bkv     = (const float*)d_in[4];
    const float* Wq      = (const float*)d_in[5];
    const float* bq      = (const float*)d_in[6];
    float* out = (float*)d_out;

    const int SMEM_OUT = (32 * 516 + 32 * 68) * 4;
    cudaFuncSetAttribute(k_phase1, cudaFuncAttributeMaxDynamicSharedMemorySize, SMEM_P1_BYTES);
    cudaFuncSetAttribute(k_gemmB,  cudaFuncAttributeMaxDynamicSharedMemorySize, SMEM_GB_BYTES);
    cudaFuncSetAttribute(k_out,    cudaFuncAttributeMaxDynamicSharedMemorySize, SMEM_OUT);

    k_xcvt<<<Bn * Sn * D / (256 * 8), 256>>>(X);
    k_qp<<<dim3(4, Bn), 256>>>(queries, Wq, bq);
    k_qt<<<dim3(4, Hn, Bn), 512>>>(Wkv, bkv);
    k_phase1<<<dim3(NC, Bn), 512, SMEM_P1_BYTES>>>(masks);
    k_den<<<Bn, 256>>>();
    k_gemmB<<<dim3(8, 2, Bn), 512, SMEM_GB_BYTES>>>();
    k_ared<<<1024, 256>>>();
    k_out<<<dim3(Hn, Bn), 256, SMEM_OUT>>>(Wkv, bkv, out);
}

// round 14
// speedup vs baseline: 1.4305x; 1.2858x over previous
#include <cuda_runtime.h>
#include <cuda_fp16.h>
#include <math.h>
#include <stdint.h>

#define Bn 8
#define Sn 4096
#define Qn 32
#define Hn 8
#define D  512
#define R  256
#define SC 128
#define NC 32
#define INV_SQRT_D 0.044194173824159216f
#define ELU_CLIP 15.0f
#define ESCALE 0.0078125f          // 2^-7

// ---- phase1 smem: QH 256x40, XH 128x40 halfs ----
#define OFF_MASK 0
#define OFF_PSUM 512
#define OFF_PIPE 4096
#define P1_QH 0
#define P1_XH 20480
#define STAGE_P1 30720
#define SMEM_P1_BYTES (OFF_PIPE + 2 * STAGE_P1)   // 65536

// ---- gemmB smem: EF 256x72, XH 64x72 halfs ----
#define GB_EF 0
#define GB_XH 36864
#define STAGE_GB 46080
#define SMEM_GB_BYTES (3 * STAGE_GB)              // 138240

__device__ float g_qp[Bn * Qn * D];
__device__ __align__(16) __half g_qth[Bn * R * D];
__device__ __align__(16) __half g_Xh[Bn * Sn * D];
__device__ __align__(16) __half g_ef[Bn * 2 * NC * 128 * 128];  // e * 2^-7
__device__ float g_u0[Bn * R];
__device__ float g_dp[Bn * NC * R];
__device__ float g_den[Bn * R];
__device__ float g_Ap2[2 * Bn * R * D];
__device__ float g_An[Bn * R * D];

static __device__ __forceinline__ uint32_t smem_u32(const void* p) {
    return (uint32_t)__cvta_generic_to_shared(p);
}
static __device__ __forceinline__ void ldsm4(uint32_t* r, uint32_t a) {
    asm volatile("ldmatrix.sync.aligned.m8n8.x4.shared.b16 {%0,%1,%2,%3}, [%4];"
                 : "=r"(r[0]), "=r"(r[1]), "=r"(r[2]), "=r"(r[3]) : "r"(a));
}
static __device__ __forceinline__ void ldsm4t(uint32_t* r, uint32_t a) {
    asm volatile("ldmatrix.sync.aligned.m8n8.x4.trans.shared.b16 {%0,%1,%2,%3}, [%4];"
                 : "=r"(r[0]), "=r"(r[1]), "=r"(r[2]), "=r"(r[3]) : "r"(a));
}
static __device__ __forceinline__ void mma_f16(float* c, const uint32_t* a, uint32_t b0, uint32_t b1) {
    asm volatile(
        "mma.sync.aligned.m16n8k16.row.col.f32.f16.f16.f32 "
        "{%0,%1,%2,%3}, {%4,%5,%6,%7}, {%8,%9}, {%0,%1,%2,%3};"
        : "+f"(c[0]), "+f"(c[1]), "+f"(c[2]), "+f"(c[3])
        : "r"(a[0]), "r"(a[1]), "r"(a[2]), "r"(a[3]), "r"(b0), "r"(b1));
}
static __device__ __forceinline__ void cpa16(uint32_t dst, const void* src) {
    asm volatile("cp.async.cg.shared.global [%0], [%1], 16;" :: "r"(dst), "l"(src));
}
static __device__ __forceinline__ void cpa_commit() {
    asm volatile("cp.async.commit_group;");
}
static __device__ __forceinline__ uint32_t cvt2h(float lo_val, float hi_val) {
    uint32_t r;
    asm("cvt.rn.f16x2.f32 %0, %1, %2;" : "=r"(r) : "f"(hi_val), "f"(lo_val));
    return r;
}
static __device__ __forceinline__ float eterm(float u, float mk) {
    float uv = u * INV_SQRT_D;
    float el = uv > 0.f ? fminf(uv, ELU_CLIP) : (__expf(uv) - 1.f);
    return __expf(el) * mk;
}

// ---------------- K0: X -> fp16 ----------------
__global__ void __launch_bounds__(256) k_xcvt(const float* __restrict__ X) {
    size_t base = (size_t)(blockIdx.x * 256 + threadIdx.x) * 8;
    float4 v0 = *(const float4*)(X + base);
    float4 v1 = *(const float4*)(X + base + 4);
    uint32_t hp[4];
    hp[0] = cvt2h(v0.x, v0.y);
    hp[1] = cvt2h(v0.z, v0.w);
    hp[2] = cvt2h(v1.x, v1.y);
    hp[3] = cvt2h(v1.z, v1.w);
    *(uint4*)(g_Xh + base) = make_uint4(hp[0], hp[1], hp[2], hp[3]);
}

// ---------------- K1: qp = queries @ Wq^T + bq ----------------
__global__ void __launch_bounds__(256) k_qp(const float* __restrict__ queries,
                                            const float* __restrict__ Wq,
                                            const float* __restrict__ bq) {
    const int ct = blockIdx.x, b = blockIdx.y;
    __shared__ float Qs[32 * 17];
    __shared__ float Ws[16 * 132];
    const int t = threadIdx.x, tx = t & 15, ty = t >> 4;
    float acc[2][8];
#pragma unroll
    for (int i = 0; i < 2; i++)
#pragma unroll
        for (int j = 0; j < 8; j++) acc[i][j] = 0.f;

    for (int k0 = 0; k0 < D; k0 += 16) {
        __syncthreads();
        if (t < 128) {
            int qi = t >> 2, kq = t & 3;
            float4 v = *(const float4*)(queries + (b * Qn + qi) * D + k0 + kq * 4);
            Qs[qi * 17 + kq * 4 + 0] = v.x;
            Qs[qi * 17 + kq * 4 + 1] = v.y;
            Qs[qi * 17 + kq * 4 + 2] = v.z;
            Qs[qi * 17 + kq * 4 + 3] = v.w;
        }
#pragma unroll
        for (int it = 0; it < 2; it++) {
            int idx = t + it * 256;
            int c = idx >> 2, kq = idx & 3;
            float4 v = *(const float4*)(Wq + (ct * 128 + c) * D + k0 + kq * 4);
            Ws[(kq * 4 + 0) * 132 + c] = v.x;
            Ws[(kq * 4 + 1) * 132 + c] = v.y;
            Ws[(kq * 4 + 2) * 132 + c] = v.z;
            Ws[(kq * 4 + 3) * 132 + c] = v.w;
        }
        __syncthreads();
#pragma unroll
        for (int k = 0; k < 16; k++) {
            float a0 = Qs[(ty * 2 + 0) * 17 + k];
            float a1 = Qs[(ty * 2 + 1) * 17 + k];
            float bb[8];
            *(float4*)&bb[0] = *(const float4*)&Ws[k * 132 + tx * 8];
            *(float4*)&bb[4] = *(const float4*)&Ws[k * 132 + tx * 8 + 4];
#pragma unroll
            for (int j = 0; j < 8; j++) {
                acc[0][j] = fmaf(a0, bb[j], acc[0][j]);
                acc[1][j] = fmaf(a1, bb[j], acc[1][j]);
            }
        }
    }
#pragma unroll
    for (int i = 0; i < 2; i++)
#pragma unroll
        for (int j = 0; j < 8; j++) {
            int c = ct * 128 + tx * 8 + j;
            g_qp[(b * Qn + ty * 2 + i) * D + c] = acc[i][j] + __ldg(&bq[c]);
        }
}

// ---------------- K2: qt -> fp16; u0 ----------------
__global__ void __launch_bounds__(512) k_qt(const float* __restrict__ Wkv,
                                            const float* __restrict__ bkv) {
    const int qi0 = blockIdx.x * 8, h = blockIdx.y, b = blockIdx.z;
    __shared__ float qps[8 * 64];
    const int t = threadIdx.x;
    if (t < 128) {
        int qi = t >> 4, dq = t & 15;
        *(float4*)&qps[qi * 64 + dq * 4] =
            *(const float4*)(g_qp + (b * Qn + qi0 + qi) * D + h * 64 + dq * 4);
    }
    __syncthreads();
    if (t < 8) {
        float s = 0.f;
#pragma unroll 8
        for (int d = 0; d < 64; d++) s = fmaf(qps[t * 64 + d], __ldg(&bkv[h * 64 + d]), s);
        g_u0[b * R + h * Qn + qi0 + t] = s;
    }
    float acc[8];
#pragma unroll
    for (int i = 0; i < 8; i++) acc[i] = 0.f;
#pragma unroll 8
    for (int d = 0; d < 64; d++) {
        float w = __ldg(&Wkv[(h * 64 + d) * D + t]);
#pragma unroll
        for (int i = 0; i < 8; i++) acc[i] = fmaf(qps[i * 64 + d], w, acc[i]);
    }
#pragma unroll
    for (int i = 0; i < 8; i++)
        g_qth[(b * R + h * Qn + qi0 + i) * D + t] = __float2half_rn(acc[i]);
}

// ---------------- K3: phase1 — u = qt @ Xc^T (1-term fp16), e -> global ----------------
// 16 warps: p = w>>3; within p: 4 row-warps (32 rows) x 2 col-warps (64 cols)
__global__ void __launch_bounds__(512, 1) k_phase1(const float* __restrict__ masks) {
    const int ch = blockIdx.x, b = blockIdx.y, s0 = ch * SC;
    extern __shared__ char smraw[];
    float* mask_s = (float*)(smraw + OFF_MASK);
    float* psum   = (float*)(smraw + OFF_PSUM);   // [p][wc][128]

    const int t = threadIdx.x, w = t >> 5, l = t & 31;
    const int p = w >> 3, wr = w & 3, wc = (w >> 2) & 1;
    const uint32_t smb = smem_u32(smraw);

    if (t < 128) mask_s[t] = masks[b * Sn + s0 + t];

    const __half* xhb = g_Xh + (size_t)(b * Sn + s0) * D;
    const __half* qhb = g_qth + (size_t)(b * R) * D;

    float cu[2][8][4];
#pragma unroll
    for (int m = 0; m < 2; m++)
#pragma unroll
        for (int j = 0; j < 8; j++)
#pragma unroll
            for (int i = 0; i < 4; i++) cu[m][j][i] = 0.f;

    auto load_stage = [&](int kc, int slot) {
        uint32_t sb = smb + OFF_PIPE + slot * STAGE_P1;
        int d0 = kc * 32;
#pragma unroll
        for (int it = 0; it < 2; it++) {
            int idx = it * 512 + t;
            int row = idx >> 2, c16 = idx & 3;
            cpa16(sb + P1_QH + row * 80 + c16 * 16, qhb + row * D + d0 + c16 * 8);
        }
        {
            int row = t >> 2, c16 = t & 3;
            cpa16(sb + P1_XH + row * 80 + c16 * 16, xhb + row * D + d0 + c16 * 8);
        }
        cpa_commit();
    };

    load_stage(0, 0);
    for (int kc = 0; kc < 16; kc++) {
        if (kc + 1 < 16) {
            load_stage(kc + 1, (kc + 1) & 1);
            asm volatile("cp.async.wait_group 1;");
        } else {
            asm volatile("cp.async.wait_group 0;");
        }
        __syncthreads();
        uint32_t base = smb + OFF_PIPE + (kc & 1) * STAGE_P1;
        uint32_t qtH_b = base + P1_QH;
        uint32_t xH_b = base + P1_XH;
#pragma unroll
        for (int ks = 0; ks < 2; ks++) {
            const int k0 = ks * 16;
            uint32_t ah[2][4];
#pragma unroll
            for (int m = 0; m < 2; m++) {
                uint32_t aoff = (uint32_t)((p * 128 + wr * 32 + m * 16 + (l & 15)) * 40 +
                                           k0 + ((l >> 4) << 3)) * 2;
                ldsm4(ah[m], qtH_b + aoff);
            }
#pragma unroll
            for (int jb = 0; jb < 4; jb++) {
                uint32_t boff = (uint32_t)((wc * 64 + jb * 16 + ((l >> 4) << 3) + (l & 7)) * 40 +
                                           k0 + (((l >> 3) & 1) << 3)) * 2;
                uint32_t bh[4];
                ldsm4(bh, xH_b + boff);
#pragma unroll
                for (int m = 0; m < 2; m++) {
                    mma_f16(cu[m][2 * jb], ah[m], bh[0], bh[1]);
                    mma_f16(cu[m][2 * jb + 1], ah[m], bh[2], bh[3]);
                }
            }
        }
        __syncthreads();
    }

    // epilogue: u -> e (scaled fp16), denom partials
    const size_t eb = ((size_t)(b * 2 + p) * NC + ch) * 16384;
#pragma unroll
    for (int m = 0; m < 2; m++) {
        const int rr = wr * 32 + m * 16 + (l >> 2);
        float u0a = __ldg(&g_u0[b * R + p * 128 + rr]);
        float u0b = __ldg(&g_u0[b * R + p * 128 + rr + 8]);
        float sum0 = 0.f, sum1 = 0.f;
#pragma unroll
        for (int j = 0; j < 8; j++) {
            int col = wc * 64 + j * 8 + 2 * (l & 3);
            float m0 = mask_s[col];
            float m1 = mask_s[col + 1];
            float e0 = eterm(cu[m][j][0] + u0a, m0);
            float e1 = eterm(cu[m][j][1] + u0a, m1);
            float e2 = eterm(cu[m][j][2] + u0b, m0);
            float e3 = eterm(cu[m][j][3] + u0b, m1);
            sum0 += e0 + e1;
            sum1 += e2 + e3;
            *(uint32_t*)(g_ef + eb + (size_t)rr * 128 + col) =
                cvt2h(e0 * ESCALE, e1 * ESCALE);
            *(uint32_t*)(g_ef + eb + (size_t)(rr + 8) * 128 + col) =
                cvt2h(e2 * ESCALE, e3 * ESCALE);
        }
        sum0 += __shfl_xor_sync(0xFFFFFFFFu, sum0, 1);
        sum0 += __shfl_xor_sync(0xFFFFFFFFu, sum0, 2);
        sum1 += __shfl_xor_sync(0xFFFFFFFFu, sum1, 1);
        sum1 += __shfl_xor_sync(0xFFFFFFFFu, sum1, 2);
        if ((l & 3) == 0) {
            psum[(p * 2 + wc) * 128 + rr] = sum0;
            psum[(p * 2 + wc) * 128 + rr + 8] = sum1;
        }
    }
    __syncthreads();
    if (t < 256) {
        int pp = t >> 7, r = t & 127;
        g_dp[(b * NC + ch) * R + pp * 128 + r] =
            psum[(pp * 2) * 128 + r] + psum[(pp * 2 + 1) * 128 + r];
    }
}

// ---------------- K4: denom reduce ----------------
__global__ void k_den() {
    const int b = blockIdx.x, r = threadIdx.x;
    float s = 0.f;
#pragma unroll
    for (int ch = 0; ch < NC; ch++) s += g_dp[(b * NC + ch) * R + r];
    g_den[b * R + r] = s;
}

// ---------------- K5: gemmB — partial A = e @ X over S-half (1-term fp16) ----------------
__global__ void __launch_bounds__(512, 1) k_gemmB() {
    const int dsl = blockIdx.x, sh = blockIdx.y, b = blockIdx.z;
    const int d0 = dsl * 64;
    extern __shared__ char smraw[];
    const uint32_t smb = smem_u32(smraw);
    const int t = threadIdx.x, w = t >> 5, l = t & 31;
    const int p = w >> 3, wr = w & 3, wc = (w >> 2) & 1;

    auto load_stage = [&](int g, int slot) {
        uint32_t sb = smb + slot * STAGE_GB;
        int s64 = sh * 32 + g;
        int ch = s64 >> 1, coloff = (s64 & 1) * 64;
#pragma unroll
        for (int it = 0; it < 4; it++) {
            int idx = it * 512 + t;
            int row = idx >> 3, c8 = idx & 7;
            int pr = row >> 7, rin = row & 127;
            const __half* src = g_ef + ((size_t)(b * 2 + pr) * NC + ch) * 16384 +
                                (size_t)rin * 128 + coloff + c8 * 8;
            cpa16(sb + GB_EF + row * 144 + c8 * 16, src);
        }
        {
            int srow = t >> 3, c8 = t & 7;
            size_t xo = ((size_t)b * Sn + s64 * 64 + srow) * D + d0 + c8 * 8;
            cpa16(sb + GB_XH + srow * 144 + c8 * 16, g_Xh + xo);
        }
        cpa_commit();
    };

    float c2[2][4][4];
#pragma unroll
    for (int m = 0; m < 2; m++)
#pragma unroll
        for (int j = 0; j < 4; j++)
#pragma unroll
            for (int i = 0; i < 4; i++) c2[m][j][i] = 0.f;

    load_stage(0, 0);
    load_stage(1, 1);

    for (int g = 0; g < 32; g++) {
        if (g + 2 < 32) {
            load_stage(g + 2, (g + 2) % 3);
            asm volatile("cp.async.wait_group 2;");
        } else if (g == 30) {
            asm volatile("cp.async.wait_group 1;");
        } else {
            asm volatile("cp.async.wait_group 0;");
        }
        __syncthreads();
        uint32_t base = smb + (g % 3) * STAGE_GB;
        uint32_t EFb = base + GB_EF;
        uint32_t XHb = base + GB_XH;
#pragma unroll
        for (int ks = 0; ks < 4; ks++) {
            const int k0 = ks * 16;
            uint32_t ah[2][4];
#pragma unroll
            for (int m = 0; m < 2; m++) {
                uint32_t aoff = (uint32_t)((p * 128 + wr * 32 + m * 16 + (l & 15)) * 72 +
                                           k0 + ((l >> 4) << 3)) * 2;
                ldsm4(ah[m], EFb + aoff);
            }
#pragma unroll
            for (int jb = 0; jb < 2; jb++) {
                uint32_t boff = (uint32_t)((k0 + (((l >> 3) & 1) << 3) + (l & 7)) * 72 +
                                           wc * 32 + jb * 16 + ((l >> 4) << 3)) * 2;
                uint32_t bh[4];
                ldsm4t(bh, XHb + boff);
#pragma unroll
                for (int m = 0; m < 2; m++) {
                    mma_f16(c2[m][2 * jb], ah[m], bh[0], bh[1]);
                    mma_f16(c2[m][2 * jb + 1], ah[m], bh[2], bh[3]);
                }
            }
        }
        __syncthreads();
    }

    // epilogue: raw partial write
#pragma unroll
    for (int m = 0; m < 2; m++) {
        const int rr = wr * 32 + m * 16 + (l >> 2);
        float* dst0 = g_Ap2 + ((size_t)(sh * Bn + b) * R + p * 128 + rr) * D +
                      d0 + wc * 32 + 2 * (l & 3);
        float* dst1 = dst0 + 8 * D;
#pragma unroll
        for (int j = 0; j < 4; j++) {
            *(float2*)(dst0 + j * 8) = make_float2(c2[m][j][0], c2[m][j][1]);
            *(float2*)(dst1 + j * 8) = make_float2(c2[m][j][2], c2[m][j][3]);
        }
    }
}

// ---------------- K5b: reduce S-half partials + normalize ----------------
__global__ void __launch_bounds__(256) k_ared() {
    int gidx = blockIdx.x * 256 + threadIdx.x;
    int b = gidx >> 15;
    int r = (gidx >> 7) & 255;
    int c4 = gidx & 127;
    const float4* A0 = (const float4*)g_Ap2;
    float4 v0 = A0[((size_t)b * R + r) * 128 + c4];
    float4 v1 = A0[((size_t)(Bn + b) * R + r) * 128 + c4];
    float inv = 128.f / g_den[b * R + r];
    float4 o;
    o.x = (v0.x + v1.x) * inv;
    o.y = (v0.y + v1.y) * inv;
    o.z = (v0.z + v1.z) * inv;
    o.w = (v0.w + v1.w) * inv;
    ((float4*)g_An)[((size_t)b * R + r) * 128 + c4] = o;
}

// ---------------- K6: out = An @ Wv^T + bv ----------------
__global__ void __launch_bounds__(256) k_out(const float* __restrict__ Wkv,
                                             const float* __restrict__ bkv,
                                             float* __restrict__ out) {
    const int h = blockIdx.x, b = blockIdx.y;
    extern __shared__ float sm[];
    float* An_s = sm;
    float* Ws   = An_s + 32 * 516;
    const int t = threadIdx.x, tx = t & 7, ty = t >> 3;

#pragma unroll
    for (int it = 0; it < 16; it++) {
        int idx = t + it * 256;
        int row = idx >> 7, cq = idx & 127;
        *(float4*)&An_s[row * 516 + cq * 4] =
            *(const float4*)(g_An + (b * R + h * Qn + row) * D + cq * 4);
    }
    float acc[8];
#pragma unroll
    for (int j = 0; j < 8; j++) acc[j] = 0.f;

    for (int kt = 0; kt < 16; kt++) {
        __syncthreads();
#pragma unroll
        for (int it = 0; it < 2; it++) {
            int idx = t * 2 + it;
            int row = idx >> 3, kq = idx & 7;
            float4 v = *(const float4*)(Wkv + (D + h * 64 + row) * D + kt * 32 + kq * 4);
            Ws[(kq * 4 + 0) * 68 + row] = v.x;
            Ws[(kq * 4 + 1) * 68 + row] = v.y;
            Ws[(kq * 4 + 2) * 68 + row] = v.z;
            Ws[(kq * 4 + 3) * 68 + row] = v.w;
        }
        __syncthreads();
#pragma unroll
        for (int k = 0; k < 32; k++) {
            float a = An_s[ty * 516 + kt * 32 + k];
            float bb[8];
            *(float4*)&bb[0] = *(const float4*)&Ws[k * 68 + tx * 8];
            *(float4*)&bb[4] = *(const float4*)&Ws[k * 68 + tx * 8 + 4];
#pragma unroll
            for (int j = 0; j < 8; j++) acc[j] = fmaf(a, bb[j], acc[j]);
        }
    }
#pragma unroll
    for (int j = 0; j < 8; j++) {
        int c = h * 64 + tx * 8 + j;
        out[(b * Qn + ty) * D + c] = acc[j] + __ldg(&bkv[D + c]);
    }
}

extern "C" void kernel_launch(void* const* d_in, const int* in_sizes, int n_in,
                              void* d_out, int out_size) {
    const float* X       = (const float*)d_in[0];
    const float* queries = (const float*)d_in[1];
    const float* masks   = (const float*)d_in[2];
    const float* Wkv     = (const float*)d_in[3];
    const float* bkv     = (const float*)d_in[4];
    const float* Wq      = (const float*)d_in[5];
    const float* bq      = (const float*)d_in[6];
    float* out = (float*)d_out;

    const int SMEM_OUT = (32 * 516 + 32 * 68) * 4;
    cudaFuncSetAttribute(k_phase1, cudaFuncAttributeMaxDynamicSharedMemorySize, SMEM_P1_BYTES);
    cudaFuncSetAttribute(k_gemmB,  cudaFuncAttributeMaxDynamicSharedMemorySize, SMEM_GB_BYTES);
    cudaFuncSetAttribute(k_out,    cudaFuncAttributeMaxDynamicSharedMemorySize, SMEM_OUT);

    k_xcvt<<<Bn * Sn * D / (256 * 8), 256>>>(X);
    k_qp<<<dim3(4, Bn), 256>>>(queries, Wq, bq);
    k_qt<<<dim3(4, Hn, Bn), 512>>>(Wkv, bkv);
    k_phase1<<<dim3(NC, Bn), 512, SMEM_P1_BYTES>>>(masks);
    k_den<<<Bn, 256>>>();
    k_gemmB<<<dim3(8, 2, Bn), 512, SMEM_GB_BYTES>>>();
    k_ared<<<1024, 256>>>();
    k_out<<<dim3(Hn, Bn), 256, SMEM_OUT>>>(Wkv, bkv, out);
}

// round 15
// speedup vs baseline: 1.5063x; 1.0530x over previous
#include <cuda_runtime.h>
#include <cuda_fp16.h>
#include <math.h>
#include <stdint.h>

#define Bn 8
#define Sn 4096
#define Qn 32
#define Hn 8
#define D  512
#define R  256
#define SC 128
#define NC 32
#define INV_SQRT_D 0.044194173824159216f
#define ELU_CLIP 15.0f
#define ESCALE 0.0078125f          // 2^-7

// ---- phase1 smem: QH 256x40, XH 128x40 halfs ----
#define OFF_MASK 0
#define OFF_PSUM 512
#define OFF_PIPE 4096
#define P1_QH 0
#define P1_XH 20480
#define STAGE_P1 30720
#define SMEM_P1_BYTES (OFF_PIPE + 2 * STAGE_P1)   // 65536

// ---- gemmB smem: EF 256x72 halfs, XH 64x136 halfs ----
#define GB_EF 0
#define GB_XH 36864
#define STAGE_GB 54272
#define SMEM_GB_BYTES (3 * STAGE_GB)              // 162816

__device__ float g_qp[Bn * Qn * D];
__device__ __align__(16) __half g_qth[Bn * R * D];
__device__ __align__(16) __half g_Xh[Bn * Sn * D];
__device__ __align__(16) __half g_ef[Bn * 2 * NC * 128 * 128];  // e * 2^-7
__device__ float g_u0[Bn * R];
__device__ float g_dp[Bn * NC * R];
__device__ float g_den[Bn * R];
__device__ float g_Ap2[4 * Bn * R * D];   // 4 S-quarter partials (16.8MB)

static __device__ __forceinline__ uint32_t smem_u32(const void* p) {
    return (uint32_t)__cvta_generic_to_shared(p);
}
static __device__ __forceinline__ void ldsm4(uint32_t* r, uint32_t a) {
    asm volatile("ldmatrix.sync.aligned.m8n8.x4.shared.b16 {%0,%1,%2,%3}, [%4];"
                 : "=r"(r[0]), "=r"(r[1]), "=r"(r[2]), "=r"(r[3]) : "r"(a));
}
static __device__ __forceinline__ void ldsm4t(uint32_t* r, uint32_t a) {
    asm volatile("ldmatrix.sync.aligned.m8n8.x4.trans.shared.b16 {%0,%1,%2,%3}, [%4];"
                 : "=r"(r[0]), "=r"(r[1]), "=r"(r[2]), "=r"(r[3]) : "r"(a));
}
static __device__ __forceinline__ void mma_f16(float* c, const uint32_t* a, uint32_t b0, uint32_t b1) {
    asm volatile(
        "mma.sync.aligned.m16n8k16.row.col.f32.f16.f16.f32 "
        "{%0,%1,%2,%3}, {%4,%5,%6,%7}, {%8,%9}, {%0,%1,%2,%3};"
        : "+f"(c[0]), "+f"(c[1]), "+f"(c[2]), "+f"(c[3])
        : "r"(a[0]), "r"(a[1]), "r"(a[2]), "r"(a[3]), "r"(b0), "r"(b1));
}
static __device__ __forceinline__ void cpa16(uint32_t dst, const void* src) {
    asm volatile("cp.async.cg.shared.global [%0], [%1], 16;" :: "r"(dst), "l"(src));
}
static __device__ __forceinline__ void cpa_commit() {
    asm volatile("cp.async.commit_group;");
}
static __device__ __forceinline__ uint32_t cvt2h(float lo_val, float hi_val) {
    uint32_t r;
    asm("cvt.rn.f16x2.f32 %0, %1, %2;" : "=r"(r) : "f"(hi_val), "f"(lo_val));
    return r;
}
static __device__ __forceinline__ float eterm(float u, float mk) {
    float uv = u * INV_SQRT_D;
    float el = uv > 0.f ? fminf(uv, ELU_CLIP) : (__expf(uv) - 1.f);
    return __expf(el) * mk;
}

// ---------------- K0: X -> fp16 ----------------
__global__ void __launch_bounds__(256) k_xcvt(const float* __restrict__ X) {
    size_t base = (size_t)(blockIdx.x * 256 + threadIdx.x) * 8;
    float4 v0 = *(const float4*)(X + base);
    float4 v1 = *(const float4*)(X + base + 4);
    uint32_t hp[4];
    hp[0] = cvt2h(v0.x, v0.y);
    hp[1] = cvt2h(v0.z, v0.w);
    hp[2] = cvt2h(v1.x, v1.y);
    hp[3] = cvt2h(v1.z, v1.w);
    *(uint4*)(g_Xh + base) = make_uint4(hp[0], hp[1], hp[2], hp[3]);
}

// ---------------- K1: qp = queries @ Wq^T + bq ----------------
__global__ void __launch_bounds__(256) k_qp(const float* __restrict__ queries,
                                            const float* __restrict__ Wq,
                                            const float* __restrict__ bq) {
    const int ct = blockIdx.x, b = blockIdx.y;
    __shared__ float Qs[32 * 17];
    __shared__ float Ws[16 * 132];
    const int t = threadIdx.x, tx = t & 15, ty = t >> 4;
    float acc[2][8];
#pragma unroll
    for (int i = 0; i < 2; i++)
#pragma unroll
        for (int j = 0; j < 8; j++) acc[i][j] = 0.f;

    for (int k0 = 0; k0 < D; k0 += 16) {
        __syncthreads();
        if (t < 128) {
            int qi = t >> 2, kq = t & 3;
            float4 v = *(const float4*)(queries + (b * Qn + qi) * D + k0 + kq * 4);
            Qs[qi * 17 + kq * 4 + 0] = v.x;
            Qs[qi * 17 + kq * 4 + 1] = v.y;
            Qs[qi * 17 + kq * 4 + 2] = v.z;
            Qs[qi * 17 + kq * 4 + 3] = v.w;
        }
#pragma unroll
        for (int it = 0; it < 2; it++) {
            int idx = t + it * 256;
            int c = idx >> 2, kq = idx & 3;
            float4 v = *(const float4*)(Wq + (ct * 128 + c) * D + k0 + kq * 4);
            Ws[(kq * 4 + 0) * 132 + c] = v.x;
            Ws[(kq * 4 + 1) * 132 + c] = v.y;
            Ws[(kq * 4 + 2) * 132 + c] = v.z;
            Ws[(kq * 4 + 3) * 132 + c] = v.w;
        }
        __syncthreads();
#pragma unroll
        for (int k = 0; k < 16; k++) {
            float a0 = Qs[(ty * 2 + 0) * 17 + k];
            float a1 = Qs[(ty * 2 + 1) * 17 + k];
            float bb[8];
            *(float4*)&bb[0] = *(const float4*)&Ws[k * 132 + tx * 8];
            *(float4*)&bb[4] = *(const float4*)&Ws[k * 132 + tx * 8 + 4];
#pragma unroll
            for (int j = 0; j < 8; j++) {
                acc[0][j] = fmaf(a0, bb[j], acc[0][j]);
                acc[1][j] = fmaf(a1, bb[j], acc[1][j]);
            }
        }
    }
#pragma unroll
    for (int i = 0; i < 2; i++)
#pragma unroll
        for (int j = 0; j < 8; j++) {
            int c = ct * 128 + tx * 8 + j;
            g_qp[(b * Qn + ty * 2 + i) * D + c] = acc[i][j] + __ldg(&bq[c]);
        }
}

// ---------------- K2: qt -> fp16; u0 ----------------
__global__ void __launch_bounds__(512) k_qt(const float* __restrict__ Wkv,
                                            const float* __restrict__ bkv) {
    const int qi0 = blockIdx.x * 8, h = blockIdx.y, b = blockIdx.z;
    __shared__ float qps[8 * 64];
    const int t = threadIdx.x;
    if (t < 128) {
        int qi = t >> 4, dq = t & 15;
        *(float4*)&qps[qi * 64 + dq * 4] =
            *(const float4*)(g_qp + (b * Qn + qi0 + qi) * D + h * 64 + dq * 4);
    }
    __syncthreads();
    if (t < 8) {
        float s = 0.f;
#pragma unroll 8
        for (int d = 0; d < 64; d++) s = fmaf(qps[t * 64 + d], __ldg(&bkv[h * 64 + d]), s);
        g_u0[b * R + h * Qn + qi0 + t] = s;
    }
    float acc[8];
#pragma unroll
    for (int i = 0; i < 8; i++) acc[i] = 0.f;
#pragma unroll 8
    for (int d = 0; d < 64; d++) {
        float w = __ldg(&Wkv[(h * 64 + d) * D + t]);
#pragma unroll
        for (int i = 0; i < 8; i++) acc[i] = fmaf(qps[i * 64 + d], w, acc[i]);
    }
#pragma unroll
    for (int i = 0; i < 8; i++)
        g_qth[(b * R + h * Qn + qi0 + i) * D + t] = __float2half_rn(acc[i]);
}

// ---------------- K3: phase1 — u = qt @ Xc^T (1-term fp16), e -> global ----------------
__global__ void __launch_bounds__(512, 1) k_phase1(const float* __restrict__ masks) {
    const int ch = blockIdx.x, b = blockIdx.y, s0 = ch * SC;
    extern __shared__ char smraw[];
    float* mask_s = (float*)(smraw + OFF_MASK);
    float* psum   = (float*)(smraw + OFF_PSUM);

    const int t = threadIdx.x, w = t >> 5, l = t & 31;
    const int p = w >> 3, wr = w & 3, wc = (w >> 2) & 1;
    const uint32_t smb = smem_u32(smraw);

    if (t < 128) mask_s[t] = masks[b * Sn + s0 + t];

    const __half* xhb = g_Xh + (size_t)(b * Sn + s0) * D;
    const __half* qhb = g_qth + (size_t)(b * R) * D;

    float cu[2][8][4];
#pragma unroll
    for (int m = 0; m < 2; m++)
#pragma unroll
        for (int j = 0; j < 8; j++)
#pragma unroll
            for (int i = 0; i < 4; i++) cu[m][j][i] = 0.f;

    auto load_stage = [&](int kc, int slot) {
        uint32_t sb = smb + OFF_PIPE + slot * STAGE_P1;
        int d0 = kc * 32;
#pragma unroll
        for (int it = 0; it < 2; it++) {
            int idx = it * 512 + t;
            int row = idx >> 2, c16 = idx & 3;
            cpa16(sb + P1_QH + row * 80 + c16 * 16, qhb + row * D + d0 + c16 * 8);
        }
        {
            int row = t >> 2, c16 = t & 3;
            cpa16(sb + P1_XH + row * 80 + c16 * 16, xhb + row * D + d0 + c16 * 8);
        }
        cpa_commit();
    };

    load_stage(0, 0);
    for (int kc = 0; kc < 16; kc++) {
        if (kc + 1 < 16) {
            load_stage(kc + 1, (kc + 1) & 1);
            asm volatile("cp.async.wait_group 1;");
        } else {
            asm volatile("cp.async.wait_group 0;");
        }
        __syncthreads();
        uint32_t base = smb + OFF_PIPE + (kc & 1) * STAGE_P1;
        uint32_t qtH_b = base + P1_QH;
        uint32_t xH_b = base + P1_XH;
#pragma unroll
        for (int ks = 0; ks < 2; ks++) {
            const int k0 = ks * 16;
            uint32_t ah[2][4];
#pragma unroll
            for (int m = 0; m < 2; m++) {
                uint32_t aoff = (uint32_t)((p * 128 + wr * 32 + m * 16 + (l & 15)) * 40 +
                                           k0 + ((l >> 4) << 3)) * 2;
                ldsm4(ah[m], qtH_b + aoff);
            }
#pragma unroll
            for (int jb = 0; jb < 4; jb++) {
                uint32_t boff = (uint32_t)((wc * 64 + jb * 16 + ((l >> 4) << 3) + (l & 7)) * 40 +
                                           k0 + (((l >> 3) & 1) << 3)) * 2;
                uint32_t bh[4];
                ldsm4(bh, xH_b + boff);
#pragma unroll
                for (int m = 0; m < 2; m++) {
                    mma_f16(cu[m][2 * jb], ah[m], bh[0], bh[1]);
                    mma_f16(cu[m][2 * jb + 1], ah[m], bh[2], bh[3]);
                }
            }
        }
        __syncthreads();
    }

    const size_t eb = ((size_t)(b * 2 + p) * NC + ch) * 16384;
#pragma unroll
    for (int m = 0; m < 2; m++) {
        const int rr = wr * 32 + m * 16 + (l >> 2);
        float u0a = __ldg(&g_u0[b * R + p * 128 + rr]);
        float u0b = __ldg(&g_u0[b * R + p * 128 + rr + 8]);
        float sum0 = 0.f, sum1 = 0.f;
#pragma unroll
        for (int j = 0; j < 8; j++) {
            int col = wc * 64 + j * 8 + 2 * (l & 3);
            float m0 = mask_s[col];
            float m1 = mask_s[col + 1];
            float e0 = eterm(cu[m][j][0] + u0a, m0);
            float e1 = eterm(cu[m][j][1] + u0a, m1);
            float e2 = eterm(cu[m][j][2] + u0b, m0);
            float e3 = eterm(cu[m][j][3] + u0b, m1);
            sum0 += e0 + e1;
            sum1 += e2 + e3;
            *(uint32_t*)(g_ef + eb + (size_t)rr * 128 + col) =
                cvt2h(e0 * ESCALE, e1 * ESCALE);
            *(uint32_t*)(g_ef + eb + (size_t)(rr + 8) * 128 + col) =
                cvt2h(e2 * ESCALE, e3 * ESCALE);
        }
        sum0 += __shfl_xor_sync(0xFFFFFFFFu, sum0, 1);
        sum0 += __shfl_xor_sync(0xFFFFFFFFu, sum0, 2);
        sum1 += __shfl_xor_sync(0xFFFFFFFFu, sum1, 1);
        sum1 += __shfl_xor_sync(0xFFFFFFFFu, sum1, 2);
        if ((l & 3) == 0) {
            psum[(p * 2 + wc) * 128 + rr] = sum0;
            psum[(p * 2 + wc) * 128 + rr + 8] = sum1;
        }
    }
    __syncthreads();
    if (t < 256) {
        int pp = t >> 7, r = t & 127;
        g_dp[(b * NC + ch) * R + pp * 128 + r] =
            psum[(pp * 2) * 128 + r] + psum[(pp * 2 + 1) * 128 + r];
    }
}

// ---------------- K4: denom reduce ----------------
__global__ void k_den() {
    const int b = blockIdx.x, r = threadIdx.x;
    float s = 0.f;
#pragma unroll
    for (int ch = 0; ch < NC; ch++) s += g_dp[(b * NC + ch) * R + r];
    g_den[b * R + r] = s;
}

// ---------------- K5: gemmB — partial A = e @ X over S-quarter, d-slice 128 ----------------
// grid (4 dsl, 4 sh, 8 b); 16 warps: p = w>>3; 4 row-warps x 2 col-warps (64 of 128 cols)
__global__ void __launch_bounds__(512, 1) k_gemmB() {
    const int dsl = blockIdx.x, sh = blockIdx.y, b = blockIdx.z;
    const int d0 = dsl * 128;
    extern __shared__ char smraw[];
    const uint32_t smb = smem_u32(smraw);
    const int t = threadIdx.x, w = t >> 5, l = t & 31;
    const int p = w >> 3, wr = w & 3, wc = (w >> 2) & 1;

    auto load_stage = [&](int g, int slot) {
        uint32_t sb = smb + slot * STAGE_GB;
        int s64 = sh * 16 + g;
        int ch = s64 >> 1, coloff = (s64 & 1) * 64;
#pragma unroll
        for (int it = 0; it < 4; it++) {
            int idx = it * 512 + t;
            int row = idx >> 3, c8 = idx & 7;
            int pr = row >> 7, rin = row & 127;
            const __half* src = g_ef + ((size_t)(b * 2 + pr) * NC + ch) * 16384 +
                                (size_t)rin * 128 + coloff + c8 * 8;
            cpa16(sb + GB_EF + row * 144 + c8 * 16, src);
        }
#pragma unroll
        for (int it = 0; it < 2; it++) {
            int idx = it * 512 + t;
            int srow = idx >> 4, c8 = idx & 15;
            size_t xo = ((size_t)b * Sn + s64 * 64 + srow) * D + d0 + c8 * 8;
            cpa16(sb + GB_XH + srow * 272 + c8 * 16, g_Xh + xo);
        }
        cpa_commit();
    };

    float c2[2][8][4];
#pragma unroll
    for (int m = 0; m < 2; m++)
#pragma unroll
        for (int j = 0; j < 8; j++)
#pragma unroll
            for (int i = 0; i < 4; i++) c2[m][j][i] = 0.f;

    load_stage(0, 0);
    load_stage(1, 1);

    for (int g = 0; g < 16; g++) {
        if (g + 2 < 16) {
            load_stage(g + 2, (g + 2) % 3);
            asm volatile("cp.async.wait_group 2;");
        } else if (g == 14) {
            asm volatile("cp.async.wait_group 1;");
        } else {
            asm volatile("cp.async.wait_group 0;");
        }
        __syncthreads();
        uint32_t base = smb + (g % 3) * STAGE_GB;
        uint32_t EFb = base + GB_EF;
        uint32_t XHb = base + GB_XH;
#pragma unroll
        for (int ks = 0; ks < 4; ks++) {
            const int k0 = ks * 16;
            uint32_t ah[2][4];
#pragma unroll
            for (int m = 0; m < 2; m++) {
                uint32_t aoff = (uint32_t)((p * 128 + wr * 32 + m * 16 + (l & 15)) * 72 +
                                           k0 + ((l >> 4) << 3)) * 2;
                ldsm4(ah[m], EFb + aoff);
            }
#pragma unroll
            for (int jb = 0; jb < 4; jb++) {
                uint32_t boff = (uint32_t)((k0 + (((l >> 3) & 1) << 3) + (l & 7)) * 136 +
                                           wc * 64 + jb * 16 + ((l >> 4) << 3)) * 2;
                uint32_t bh[4];
                ldsm4t(bh, XHb + boff);
#pragma unroll
                for (int m = 0; m < 2; m++) {
                    mma_f16(c2[m][2 * jb], ah[m], bh[0], bh[1]);
                    mma_f16(c2[m][2 * jb + 1], ah[m], bh[2], bh[3]);
                }
            }
        }
        __syncthreads();
    }

    // epilogue: raw partial write
#pragma unroll
    for (int m = 0; m < 2; m++) {
        const int rr = wr * 32 + m * 16 + (l >> 2);
        float* dst0 = g_Ap2 + ((size_t)(sh * Bn + b) * R + p * 128 + rr) * D +
                      d0 + wc * 64 + 2 * (l & 3);
        float* dst1 = dst0 + 8 * D;
#pragma unroll
        for (int j = 0; j < 8; j++) {
            *(float2*)(dst0 + j * 8) = make_float2(c2[m][j][0], c2[m][j][1]);
            *(float2*)(dst1 + j * 8) = make_float2(c2[m][j][2], c2[m][j][3]);
        }
    }
}

// ---------------- K6: out = ((sum_sh Ap2) * 128/den) @ Wv^T + bv ----------------
__global__ void __launch_bounds__(256) k_out(const float* __restrict__ Wkv,
                                             const float* __restrict__ bkv,
                                             float* __restrict__ out) {
    const int h = blockIdx.x, b = blockIdx.y;
    extern __shared__ float sm[];
    float* An_s = sm;
    float* Ws   = An_s + 32 * 516;
    const int t = threadIdx.x, tx = t & 7, ty = t >> 3;
    const size_t slab = (size_t)Bn * R * D / 4;   // float4 stride per sh

#pragma unroll
    for (int it = 0; it < 16; it++) {
        int idx = t + it * 256;
        int row = idx >> 7, cq = idx & 127;
        size_t a0 = (((size_t)b * R + h * Qn + row) * D) / 4 + cq;
        const float4* Ap4 = (const float4*)g_Ap2;
        float4 s = Ap4[a0];
        float4 v1 = Ap4[a0 + slab];
        float4 v2 = Ap4[a0 + 2 * slab];
        float4 v3 = Ap4[a0 + 3 * slab];
        s.x += v1.x + v2.x + v3.x;
        s.y += v1.y + v2.y + v3.y;
        s.z += v1.z + v2.z + v3.z;
        s.w += v1.w + v2.w + v3.w;
        float inv = 128.f / __ldg(&g_den[b * R + h * Qn + row]);
        An_s[row * 516 + cq * 4 + 0] = s.x * inv;
        An_s[row * 516 + cq * 4 + 1] = s.y * inv;
        An_s[row * 516 + cq * 4 + 2] = s.z * inv;
        An_s[row * 516 + cq * 4 + 3] = s.w * inv;
    }
    float acc[8];
#pragma unroll
    for (int j = 0; j < 8; j++) acc[j] = 0.f;

    for (int kt = 0; kt < 16; kt++) {
        __syncthreads();
#pragma unroll
        for (int it = 0; it < 2; it++) {
            int idx = t * 2 + it;
            int row = idx >> 3, kq = idx & 7;
            float4 v = *(const float4*)(Wkv + (D + h * 64 + row) * D + kt * 32 + kq * 4);
            Ws[(kq * 4 + 0) * 68 + row] = v.x;
            Ws[(kq * 4 + 1) * 68 + row] = v.y;
            Ws[(kq * 4 + 2) * 68 + row] = v.z;
            Ws[(kq * 4 + 3) * 68 + row] = v.w;
        }
        __syncthreads();
#pragma unroll
        for (int k = 0; k < 32; k++) {
            float a = An_s[ty * 516 + kt * 32 + k];
            float bb[8];
            *(float4*)&bb[0] = *(const float4*)&Ws[k * 68 + tx * 8];
            *(float4*)&bb[4] = *(const float4*)&Ws[k * 68 + tx * 8 + 4];
#pragma unroll
            for (int j = 0; j < 8; j++) acc[j] = fmaf(a, bb[j], acc[j]);
        }
    }
#pragma unroll
    for (int j = 0; j < 8; j++) {
        int c = h * 64 + tx * 8 + j;
        out[(b * Qn + ty) * D + c] = acc[j] + __ldg(&bkv[D + c]);
    }
}

extern "C" void kernel_launch(void* const* d_in, const int* in_sizes, int n_in,
                              void* d_out, int out_size) {
    const float* X       = (const float*)d_in[0];
    const float* queries = (const float*)d_in[1];
    const float* masks   = (const float*)d_in[2];
    const float* Wkv     = (const float*)d_in[3];
    const float* bkv     = (const float*)d_in[4];
    const float* Wq      = (const float*)d_in[5];
    const float* bq      = (const float*)d_in[6];
    float* out = (float*)d_out;

    const int SMEM_OUT = (32 * 516 + 32 * 68) * 4;
    cudaFuncSetAttribute(k_phase1, cudaFuncAttributeMaxDynamicSharedMemorySize, SMEM_P1_BYTES);
    cudaFuncSetAttribute(k_gemmB,  cudaFuncAttributeMaxDynamicSharedMemorySize, SMEM_GB_BYTES);
    cudaFuncSetAttribute(k_out,    cudaFuncAttributeMaxDynamicSharedMemorySize, SMEM_OUT);

    k_xcvt<<<Bn * Sn * D / (256 * 8), 256>>>(X);
    k_qp<<<dim3(4, Bn), 256>>>(queries, Wq, bq);
    k_qt<<<dim3(4, Hn, Bn), 512>>>(Wkv, bkv);
    k_phase1<<<dim3(NC, Bn), 512, SMEM_P1_BYTES>>>(masks);
    k_den<<<Bn, 256>>>();
    k_gemmB<<<dim3(4, 4, Bn), 512, SMEM_GB_BYTES>>>();
    k_out<<<dim3(Hn, Bn), 256, SMEM_OUT>>>(Wkv, bkv, out);
}

// round 16
// speedup vs baseline: 1.5521x; 1.0304x over previous
#include <cuda_runtime.h>
#include <cuda_fp16.h>
#include <math.h>
#include <stdint.h>

#define Bn 8
#define Sn 4096
#define Qn 32
#define Hn 8
#define D  512
#define R  256
#define SC 128
#define NC 32
#define INV_SQRT_D 0.044194173824159216f
#define ELU_CLIP 15.0f
#define ESCALE 0.0078125f          // 2^-7

// ---- phase1 smem: QH 256x72, XH 128x72 halfs (K=64 per stage) ----
#define OFF_MASK 0
#define OFF_PSUM 512
#define OFF_PIPE 4096
#define P1_QH 0
#define P1_XH 36864
#define STAGE_P1 55296
#define SMEM_P1_BYTES (OFF_PIPE + 2 * STAGE_P1)   // 114688

// ---- gemmB smem: EF 256x136, XH 128x136 halfs (K=128 per stage) ----
#define GB_EF 0
#define GB_XH 69632
#define STAGE_GB 104448
#define SMEM_GB_BYTES (2 * STAGE_GB)              // 208896

__device__ float g_qp[Bn * Qn * D];
__device__ __align__(16) __half g_qth[Bn * R * D];
__device__ __align__(16) __half g_Xh[Bn * Sn * D];
__device__ __align__(16) __half g_ef[Bn * 2 * NC * 128 * 128];  // e * 2^-7
__device__ float g_u0[Bn * R];
__device__ float g_dp[Bn * NC * R];
__device__ float g_den[Bn * R];
__device__ float g_Ap2[4 * Bn * R * D];   // 4 S-quarter partials

static __device__ __forceinline__ uint32_t smem_u32(const void* p) {
    return (uint32_t)__cvta_generic_to_shared(p);
}
static __device__ __forceinline__ void ldsm4(uint32_t* r, uint32_t a) {
    asm volatile("ldmatrix.sync.aligned.m8n8.x4.shared.b16 {%0,%1,%2,%3}, [%4];"
                 : "=r"(r[0]), "=r"(r[1]), "=r"(r[2]), "=r"(r[3]) : "r"(a));
}
static __device__ __forceinline__ void ldsm4t(uint32_t* r, uint32_t a) {
    asm volatile("ldmatrix.sync.aligned.m8n8.x4.trans.shared.b16 {%0,%1,%2,%3}, [%4];"
                 : "=r"(r[0]), "=r"(r[1]), "=r"(r[2]), "=r"(r[3]) : "r"(a));
}
static __device__ __forceinline__ void mma_f16(float* c, const uint32_t* a, uint32_t b0, uint32_t b1) {
    asm volatile(
        "mma.sync.aligned.m16n8k16.row.col.f32.f16.f16.f32 "
        "{%0,%1,%2,%3}, {%4,%5,%6,%7}, {%8,%9}, {%0,%1,%2,%3};"
        : "+f"(c[0]), "+f"(c[1]), "+f"(c[2]), "+f"(c[3])
        : "r"(a[0]), "r"(a[1]), "r"(a[2]), "r"(a[3]), "r"(b0), "r"(b1));
}
static __device__ __forceinline__ void cpa16(uint32_t dst, const void* src) {
    asm volatile("cp.async.cg.shared.global [%0], [%1], 16;" :: "r"(dst), "l"(src));
}
static __device__ __forceinline__ void cpa_commit() {
    asm volatile("cp.async.commit_group;");
}
static __device__ __forceinline__ uint32_t cvt2h(float lo_val, float hi_val) {
    uint32_t r;
    asm("cvt.rn.f16x2.f32 %0, %1, %2;" : "=r"(r) : "f"(hi_val), "f"(lo_val));
    return r;
}
static __device__ __forceinline__ float eterm(float u, float mk) {
    float uv = u * INV_SQRT_D;
    float el = uv > 0.f ? fminf(uv, ELU_CLIP) : (__expf(uv) - 1.f);
    return __expf(el) * mk;
}

// ---------------- K0: X -> fp16 ----------------
__global__ void __launch_bounds__(256) k_xcvt(const float* __restrict__ X) {
    size_t base = (size_t)(blockIdx.x * 256 + threadIdx.x) * 8;
    float4 v0 = *(const float4*)(X + base);
    float4 v1 = *(const float4*)(X + base + 4);
    uint32_t hp[4];
    hp[0] = cvt2h(v0.x, v0.y);
    hp[1] = cvt2h(v0.z, v0.w);
    hp[2] = cvt2h(v1.x, v1.y);
    hp[3] = cvt2h(v1.z, v1.w);
    *(uint4*)(g_Xh + base) = make_uint4(hp[0], hp[1], hp[2], hp[3]);
}

// ---------------- K1: qp = queries @ Wq^T + bq ----------------
__global__ void __launch_bounds__(256) k_qp(const float* __restrict__ queries,
                                            const float* __restrict__ Wq,
                                            const float* __restrict__ bq) {
    const int ct = blockIdx.x, b = blockIdx.y;
    __shared__ float Qs[32 * 17];
    __shared__ float Ws[16 * 132];
    const int t = threadIdx.x, tx = t & 15, ty = t >> 4;
    float acc[2][8];
#pragma unroll
    for (int i = 0; i < 2; i++)
#pragma unroll
        for (int j = 0; j < 8; j++) acc[i][j] = 0.f;

    for (int k0 = 0; k0 < D; k0 += 16) {
        __syncthreads();
        if (t < 128) {
            int qi = t >> 2, kq = t & 3;
            float4 v = *(const float4*)(queries + (b * Qn + qi) * D + k0 + kq * 4);
            Qs[qi * 17 + kq * 4 + 0] = v.x;
            Qs[qi * 17 + kq * 4 + 1] = v.y;
            Qs[qi * 17 + kq * 4 + 2] = v.z;
            Qs[qi * 17 + kq * 4 + 3] = v.w;
        }
#pragma unroll
        for (int it = 0; it < 2; it++) {
            int idx = t + it * 256;
            int c = idx >> 2, kq = idx & 3;
            float4 v = *(const float4*)(Wq + (ct * 128 + c) * D + k0 + kq * 4);
            Ws[(kq * 4 + 0) * 132 + c] = v.x;
            Ws[(kq * 4 + 1) * 132 + c] = v.y;
            Ws[(kq * 4 + 2) * 132 + c] = v.z;
            Ws[(kq * 4 + 3) * 132 + c] = v.w;
        }
        __syncthreads();
#pragma unroll
        for (int k = 0; k < 16; k++) {
            float a0 = Qs[(ty * 2 + 0) * 17 + k];
            float a1 = Qs[(ty * 2 + 1) * 17 + k];
            float bb[8];
            *(float4*)&bb[0] = *(const float4*)&Ws[k * 132 + tx * 8];
            *(float4*)&bb[4] = *(const float4*)&Ws[k * 132 + tx * 8 + 4];
#pragma unroll
            for (int j = 0; j < 8; j++) {
                acc[0][j] = fmaf(a0, bb[j], acc[0][j]);
                acc[1][j] = fmaf(a1, bb[j], acc[1][j]);
            }
        }
    }
#pragma unroll
    for (int i = 0; i < 2; i++)
#pragma unroll
        for (int j = 0; j < 8; j++) {
            int c = ct * 128 + tx * 8 + j;
            g_qp[(b * Qn + ty * 2 + i) * D + c] = acc[i][j] + __ldg(&bq[c]);
        }
}

// ---------------- K2: qt -> fp16; u0 ----------------
__global__ void __launch_bounds__(512) k_qt(const float* __restrict__ Wkv,
                                            const float* __restrict__ bkv) {
    const int qi0 = blockIdx.x * 8, h = blockIdx.y, b = blockIdx.z;
    __shared__ float qps[8 * 64];
    const int t = threadIdx.x;
    if (t < 128) {
        int qi = t >> 4, dq = t & 15;
        *(float4*)&qps[qi * 64 + dq * 4] =
            *(const float4*)(g_qp + (b * Qn + qi0 + qi) * D + h * 64 + dq * 4);
    }
    __syncthreads();
    if (t < 8) {
        float s = 0.f;
#pragma unroll 8
        for (int d = 0; d < 64; d++) s = fmaf(qps[t * 64 + d], __ldg(&bkv[h * 64 + d]), s);
        g_u0[b * R + h * Qn + qi0 + t] = s;
    }
    float acc[8];
#pragma unroll
    for (int i = 0; i < 8; i++) acc[i] = 0.f;
#pragma unroll 8
    for (int d = 0; d < 64; d++) {
        float w = __ldg(&Wkv[(h * 64 + d) * D + t]);
#pragma unroll
        for (int i = 0; i < 8; i++) acc[i] = fmaf(qps[i * 64 + d], w, acc[i]);
    }
#pragma unroll
    for (int i = 0; i < 8; i++)
        g_qth[(b * R + h * Qn + qi0 + i) * D + t] = __float2half_rn(acc[i]);
}

// ---------------- K3: phase1 — u = qt @ Xc^T, K=64/stage ----------------
__global__ void __launch_bounds__(512, 1) k_phase1(const float* __restrict__ masks) {
    const int ch = blockIdx.x, b = blockIdx.y, s0 = ch * SC;
    extern __shared__ char smraw[];
    float* mask_s = (float*)(smraw + OFF_MASK);
    float* psum   = (float*)(smraw + OFF_PSUM);

    const int t = threadIdx.x, w = t >> 5, l = t & 31;
    const int p = w >> 3, wr = w & 3, wc = (w >> 2) & 1;
    const uint32_t smb = smem_u32(smraw);

    if (t < 128) mask_s[t] = masks[b * Sn + s0 + t];

    const __half* xhb = g_Xh + (size_t)(b * Sn + s0) * D;
    const __half* qhb = g_qth + (size_t)(b * R) * D;

    float cu[2][8][4];
#pragma unroll
    for (int m = 0; m < 2; m++)
#pragma unroll
        for (int j = 0; j < 8; j++)
#pragma unroll
            for (int i = 0; i < 4; i++) cu[m][j][i] = 0.f;

    auto load_stage = [&](int kc, int slot) {
        uint32_t sb = smb + OFF_PIPE + slot * STAGE_P1;
        int d0 = kc * 64;
#pragma unroll
        for (int it = 0; it < 4; it++) {
            int idx = it * 512 + t;
            int row = idx >> 3, c16 = idx & 7;
            cpa16(sb + P1_QH + row * 144 + c16 * 16, qhb + row * D + d0 + c16 * 8);
        }
#pragma unroll
        for (int it = 0; it < 2; it++) {
            int idx = it * 512 + t;
            int row = idx >> 3, c16 = idx & 7;
            cpa16(sb + P1_XH + row * 144 + c16 * 16, xhb + row * D + d0 + c16 * 8);
        }
        cpa_commit();
    };

    load_stage(0, 0);
    for (int kc = 0; kc < 8; kc++) {
        if (kc + 1 < 8) {
            load_stage(kc + 1, (kc + 1) & 1);
            asm volatile("cp.async.wait_group 1;");
        } else {
            asm volatile("cp.async.wait_group 0;");
        }
        __syncthreads();
        uint32_t base = smb + OFF_PIPE + (kc & 1) * STAGE_P1;
        uint32_t qtH_b = base + P1_QH;
        uint32_t xH_b = base + P1_XH;
#pragma unroll
        for (int ks = 0; ks < 4; ks++) {
            const int k0 = ks * 16;
            uint32_t ah[2][4];
#pragma unroll
            for (int m = 0; m < 2; m++) {
                uint32_t aoff = (uint32_t)((p * 128 + wr * 32 + m * 16 + (l & 15)) * 72 +
                                           k0 + ((l >> 4) << 3)) * 2;
                ldsm4(ah[m], qtH_b + aoff);
            }
#pragma unroll
            for (int jb = 0; jb < 4; jb++) {
                uint32_t boff = (uint32_t)((wc * 64 + jb * 16 + ((l >> 4) << 3) + (l & 7)) * 72 +
                                           k0 + (((l >> 3) & 1) << 3)) * 2;
                uint32_t bh[4];
                ldsm4(bh, xH_b + boff);
#pragma unroll
                for (int m = 0; m < 2; m++) {
                    mma_f16(cu[m][2 * jb], ah[m], bh[0], bh[1]);
                    mma_f16(cu[m][2 * jb + 1], ah[m], bh[2], bh[3]);
                }
            }
        }
        __syncthreads();
    }

    const size_t eb = ((size_t)(b * 2 + p) * NC + ch) * 16384;
#pragma unroll
    for (int m = 0; m < 2; m++) {
        const int rr = wr * 32 + m * 16 + (l >> 2);
        float u0a = __ldg(&g_u0[b * R + p * 128 + rr]);
        float u0b = __ldg(&g_u0[b * R + p * 128 + rr + 8]);
        float sum0 = 0.f, sum1 = 0.f;
#pragma unroll
        for (int j = 0; j < 8; j++) {
            int col = wc * 64 + j * 8 + 2 * (l & 3);
            float m0 = mask_s[col];
            float m1 = mask_s[col + 1];
            float e0 = eterm(cu[m][j][0] + u0a, m0);
            float e1 = eterm(cu[m][j][1] + u0a, m1);
            float e2 = eterm(cu[m][j][2] + u0b, m0);
            float e3 = eterm(cu[m][j][3] + u0b, m1);
            sum0 += e0 + e1;
            sum1 += e2 + e3;
            *(uint32_t*)(g_ef + eb + (size_t)rr * 128 + col) =
                cvt2h(e0 * ESCALE, e1 * ESCALE);
            *(uint32_t*)(g_ef + eb + (size_t)(rr + 8) * 128 + col) =
                cvt2h(e2 * ESCALE, e3 * ESCALE);
        }
        sum0 += __shfl_xor_sync(0xFFFFFFFFu, sum0, 1);
        sum0 += __shfl_xor_sync(0xFFFFFFFFu, sum0, 2);
        sum1 += __shfl_xor_sync(0xFFFFFFFFu, sum1, 1);
        sum1 += __shfl_xor_sync(0xFFFFFFFFu, sum1, 2);
        if ((l & 3) == 0) {
            psum[(p * 2 + wc) * 128 + rr] = sum0;
            psum[(p * 2 + wc) * 128 + rr + 8] = sum1;
        }
    }
    __syncthreads();
    if (t < 256) {
        int pp = t >> 7, r = t & 127;
        g_dp[(b * NC + ch) * R + pp * 128 + r] =
            psum[(pp * 2) * 128 + r] + psum[(pp * 2 + 1) * 128 + r];
    }
}

// ---------------- K4: denom reduce ----------------
__global__ void k_den() {
    const int b = blockIdx.x, r = threadIdx.x;
    float s = 0.f;
#pragma unroll
    for (int ch = 0; ch < NC; ch++) s += g_dp[(b * NC + ch) * R + r];
    g_den[b * R + r] = s;
}

// ---------------- K5: gemmB — partial A = e @ X, K=128/stage (one e-chunk) ----------------
// grid (4 dsl, 4 sh, 8 b); 16 warps: p = w>>3; 4 row-warps x 2 col-warps (64 of 128 cols)
__global__ void __launch_bounds__(512, 1) k_gemmB() {
    const int dsl = blockIdx.x, sh = blockIdx.y, b = blockIdx.z;
    const int d0 = dsl * 128;
    extern __shared__ char smraw[];
    const uint32_t smb = smem_u32(smraw);
    const int t = threadIdx.x, w = t >> 5, l = t & 31;
    const int p = w >> 3, wr = w & 3, wc = (w >> 2) & 1;

    auto load_stage = [&](int g, int slot) {
        uint32_t sb = smb + slot * STAGE_GB;
        int ch = sh * 8 + g;
#pragma unroll
        for (int it = 0; it < 8; it++) {
            int idx = it * 512 + t;
            int row = idx >> 4, c8 = idx & 15;
            int pr = row >> 7, rin = row & 127;
            const __half* src = g_ef + ((size_t)(b * 2 + pr) * NC + ch) * 16384 +
                                (size_t)rin * 128 + c8 * 8;
            cpa16(sb + GB_EF + row * 272 + c8 * 16, src);
        }
#pragma unroll
        for (int it = 0; it < 4; it++) {
            int idx = it * 512 + t;
            int srow = idx >> 4, c8 = idx & 15;
            size_t xo = ((size_t)b * Sn + ch * 128 + srow) * D + d0 + c8 * 8;
            cpa16(sb + GB_XH + srow * 272 + c8 * 16, g_Xh + xo);
        }
        cpa_commit();
    };

    float c2[2][8][4];
#pragma unroll
    for (int m = 0; m < 2; m++)
#pragma unroll
        for (int j = 0; j < 8; j++)
#pragma unroll
            for (int i = 0; i < 4; i++) c2[m][j][i] = 0.f;

    load_stage(0, 0);

    for (int g = 0; g < 8; g++) {
        if (g + 1 < 8) {
            load_stage(g + 1, (g + 1) & 1);
            asm volatile("cp.async.wait_group 1;");
        } else {
            asm volatile("cp.async.wait_group 0;");
        }
        __syncthreads();
        uint32_t base = smb + (g & 1) * STAGE_GB;
        uint32_t EFb = base + GB_EF;
        uint32_t XHb = base + GB_XH;
#pragma unroll
        for (int ks = 0; ks < 8; ks++) {
            const int k0 = ks * 16;
            uint32_t ah[2][4];
#pragma unroll
            for (int m = 0; m < 2; m++) {
                uint32_t aoff = (uint32_t)((p * 128 + wr * 32 + m * 16 + (l & 15)) * 136 +
                                           k0 + ((l >> 4) << 3)) * 2;
                ldsm4(ah[m], EFb + aoff);
            }
#pragma unroll
            for (int jb = 0; jb < 4; jb++) {
                uint32_t boff = (uint32_t)((k0 + (((l >> 3) & 1) << 3) + (l & 7)) * 136 +
                                           wc * 64 + jb * 16 + ((l >> 4) << 3)) * 2;
                uint32_t bh[4];
                ldsm4t(bh, XHb + boff);
#pragma unroll
                for (int m = 0; m < 2; m++) {
                    mma_f16(c2[m][2 * jb], ah[m], bh[0], bh[1]);
                    mma_f16(c2[m][2 * jb + 1], ah[m], bh[2], bh[3]);
                }
            }
        }
        __syncthreads();
    }

    // epilogue: raw partial write
#pragma unroll
    for (int m = 0; m < 2; m++) {
        const int rr = wr * 32 + m * 16 + (l >> 2);
        float* dst0 = g_Ap2 + ((size_t)(sh * Bn + b) * R + p * 128 + rr) * D +
                      d0 + wc * 64 + 2 * (l & 3);
        float* dst1 = dst0 + 8 * D;
#pragma unroll
        for (int j = 0; j < 8; j++) {
            *(float2*)(dst0 + j * 8) = make_float2(c2[m][j][0], c2[m][j][1]);
            *(float2*)(dst1 + j * 8) = make_float2(c2[m][j][2], c2[m][j][3]);
        }
    }
}

// ---------------- K6: out = ((sum_sh Ap2) * 128/den) @ Wv^T + bv ----------------
__global__ void __launch_bounds__(256) k_out(const float* __restrict__ Wkv,
                                             const float* __restrict__ bkv,
                                             float* __restrict__ out) {
    const int h = blockIdx.x, b = blockIdx.y;
    extern __shared__ float sm[];
    float* An_s = sm;
    float* Ws   = An_s + 32 * 516;
    const int t = threadIdx.x, tx = t & 7, ty = t >> 3;
    const size_t slab = (size_t)Bn * R * D / 4;

#pragma unroll
    for (int it = 0; it < 16; it++) {
        int idx = t + it * 256;
        int row = idx >> 7, cq = idx & 127;
        size_t a0 = (((size_t)b * R + h * Qn + row) * D) / 4 + cq;
        const float4* Ap4 = (const float4*)g_Ap2;
        float4 s = Ap4[a0];
        float4 v1 = Ap4[a0 + slab];
        float4 v2 = Ap4[a0 + 2 * slab];
        float4 v3 = Ap4[a0 + 3 * slab];
        s.x += v1.x + v2.x + v3.x;
        s.y += v1.y + v2.y + v3.y;
        s.z += v1.z + v2.z + v3.z;
        s.w += v1.w + v2.w + v3.w;
        float inv = 128.f / __ldg(&g_den[b * R + h * Qn + row]);
        An_s[row * 516 + cq * 4 + 0] = s.x * inv;
        An_s[row * 516 + cq * 4 + 1] = s.y * inv;
        An_s[row * 516 + cq * 4 + 2] = s.z * inv;
        An_s[row * 516 + cq * 4 + 3] = s.w * inv;
    }
    float acc[8];
#pragma unroll
    for (int j = 0; j < 8; j++) acc[j] = 0.f;

    for (int kt = 0; kt < 16; kt++) {
        __syncthreads();
#pragma unroll
        for (int it = 0; it < 2; it++) {
            int idx = t * 2 + it;
            int row = idx >> 3, kq = idx & 7;
            float4 v = *(const float4*)(Wkv + (D + h * 64 + row) * D + kt * 32 + kq * 4);
            Ws[(kq * 4 + 0) * 68 + row] = v.x;
            Ws[(kq * 4 + 1) * 68 + row] = v.y;
            Ws[(kq * 4 + 2) * 68 + row] = v.z;
            Ws[(kq * 4 + 3) * 68 + row] = v.w;
        }
        __syncthreads();
#pragma unroll
        for (int k = 0; k < 32; k++) {
            float a = An_s[ty * 516 + kt * 32 + k];
            float bb[8];
            *(float4*)&bb[0] = *(const float4*)&Ws[k * 68 + tx * 8];
            *(float4*)&bb[4] = *(const float4*)&Ws[k * 68 + tx * 8 + 4];
#pragma unroll
            for (int j = 0; j < 8; j++) acc[j] = fmaf(a, bb[j], acc[j]);
        }
    }
#pragma unroll
    for (int j = 0; j < 8; j++) {
        int c = h * 64 + tx * 8 + j;
        out[(b * Qn + ty) * D + c] = acc[j] + __ldg(&bkv[D + c]);
    }
}

extern "C" void kernel_launch(void* const* d_in, const int* in_sizes, int n_in,
                              void* d_out, int out_size) {
    const float* X       = (const float*)d_in[0];
    const float* queries = (const float*)d_in[1];
    const float* masks   = (const float*)d_in[2];
    const float* Wkv     = (const float*)d_in[3];
    const float* bkv     = (const float*)d_in[4];
    const float* Wq      = (const float*)d_in[5];
    const float* bq      = (const float*)d_in[6];
    float* out = (float*)d_out;

    const int SMEM_OUT = (32 * 516 + 32 * 68) * 4;
    cudaFuncSetAttribute(k_phase1, cudaFuncAttributeMaxDynamicSharedMemorySize, SMEM_P1_BYTES);
    cudaFuncSetAttribute(k_gemmB,  cudaFuncAttributeMaxDynamicSharedMemorySize, SMEM_GB_BYTES);
    cudaFuncSetAttribute(k_out,    cudaFuncAttributeMaxDynamicSharedMemorySize, SMEM_OUT);

    k_xcvt<<<Bn * Sn * D / (256 * 8), 256>>>(X);
    k_qp<<<dim3(4, Bn), 256>>>(queries, Wq, bq);
    k_qt<<<dim3(4, Hn, Bn), 512>>>(Wkv, bkv);
    k_phase1<<<dim3(NC, Bn), 512, SMEM_P1_BYTES>>>(masks);
    k_den<<<Bn, 256>>>();
    k_gemmB<<<dim3(4, 4, Bn), 512, SMEM_GB_BYTES>>>();
    k_out<<<dim3(Hn, Bn), 256, SMEM_OUT>>>(Wkv, bkv, out);
}